// round 6
// baseline (speedup 1.0000x reference)
#include <cuda_runtime.h>
#include <cuda_bf16.h>

// Problem dims (fixed by the reference)
#define T_DIM 4
#define S_DIM 2048
#define D_DIM 768
#define SD (S_DIM * D_DIM)          // 1572864
#define TSD (T_DIM * SD)            // 6291456
#define N_HEADS 12
#define HEAD_DIM 64

typedef unsigned long long ull;

// Scratch (device globals: allocation-free)
__device__ float g_spk0[TSD];   // init spikes (0/1 as float)
__device__ float g_q[TSD];      // Q pre-BN, then Q spikes (in-place)
__device__ float g_k[TSD];      // K pre-BN, then K spikes (in-place)
__device__ float g_v[TSD];      // V pre-BN, then V spikes (in-place)
__device__ float g_o[TSD];      // final GEMM output pre-BN
__device__ float g_qk_raw[T_DIM * D_DIM];  // QK counts (exact integers)
__device__ float g_qk[T_DIM * D_DIM];      // talking-heads spikes (t, h*64+j)

__device__ __forceinline__ void fma2(ull &d, ull a, ull b) {
    asm("fma.rn.f32x2 %0, %1, %2, %0;" : "+l"(d) : "l"(a), "l"(b));
}

// ---------------------------------------------------------------------------
// K0: zero the QK accumulator (graph-safe, no memset API)
// ---------------------------------------------------------------------------
__global__ void k_zero_qk() {
    int i = blockIdx.x * blockDim.x + threadIdx.x;
    if (i < T_DIM * D_DIM) g_qk_raw[i] = 0.0f;
}

// ---------------------------------------------------------------------------
// K1: init_spike — IF node over T per (s,d). Exact elementwise fp32
// (bit-identical to the reference scan).
// ---------------------------------------------------------------------------
__global__ void k_init_spike(const float* __restrict__ x) {
    int idx = blockIdx.x * blockDim.x + threadIdx.x;
    if (idx >= SD) return;
    float v = 0.0f;
#pragma unroll
    for (int t = 0; t < T_DIM; t++) {
        v += x[t * SD + idx];
        float sp = (v >= 1.0f) ? 1.0f : 0.0f;
        g_spk0[t * SD + idx] = sp;
        if (sp != 0.0f) v = 0.0f;
    }
}

// ---------------------------------------------------------------------------
// GEMM: C(8192x768) = A(8192x768) @ B(768x768), fp32.
// Per-element accumulation: single accumulator, strictly ascending k, IEEE
// fma per step (fma.rn.f32x2 == two independent FFMAs) — the same chain a
// cuBLAS/Triton fp32 SIMT mainloop produces, maximizing bit-match odds.
// PHASE 0: A = g_spk0, three weights -> g_q / g_k / g_v (grid.x = 18)
// PHASE 1: A = g_v (V spikes) * g_qk mask (exact 0/1 product), B0=wo -> g_o
// Tile 128x128, BK=8, 256 threads, per-thread 8x8 via 32x fma.rn.f32x2.
// ---------------------------------------------------------------------------
template <int PHASE>
__global__ __launch_bounds__(256) void k_gemm(const float* __restrict__ B0,
                                              const float* __restrict__ B1,
                                              const float* __restrict__ B2) {
    __shared__ __align__(16) float2 As[8][128];  // A values duplicated (a,a)
    __shared__ __align__(16) float  Bs[8][128];

    const int tid = threadIdx.x;
    const float* A;
    const float* B;
    float* C;
    int col0;
    if (PHASE == 0) {
        int w = blockIdx.x / 6;
        col0 = (blockIdx.x % 6) * 128;
        A = g_spk0;
        B = (w == 0) ? B0 : ((w == 1) ? B1 : B2);
        C = (w == 0) ? g_q : ((w == 1) ? g_k : g_v);
    } else {
        col0 = blockIdx.x * 128;
        A = g_v;
        B = B0;
        C = g_o;
    }
    const int row0 = blockIdx.y * 128;

    // global-load mapping
    const int arow  = tid >> 1;          // 0..127
    const int akoff = (tid & 1) * 4;     // 0 or 4
    const int bk    = tid >> 5;          // 0..7
    const int bcol  = (tid & 31) * 4;    // 0..124

    // compute-fragment mapping (4 + 64-split for conflict-free LDS)
    const int ta4 = (tid >> 4) * 4;      // rows {ta4..+3, ta4+64..+67}
    const int tc4 = (tid & 15) * 4;      // cols {tc4..+3, tc4+64..+67}

    ull acc[8][4];
#pragma unroll
    for (int i = 0; i < 8; i++)
#pragma unroll
        for (int j = 0; j < 4; j++) acc[i][j] = 0ull;

    for (int k0 = 0; k0 < D_DIM; k0 += 8) {
        float4 av = *(const float4*)&A[(row0 + arow) * D_DIM + k0 + akoff];
        if (PHASE == 1) {
            // fuse QKV = V_spike * QK mask into the A load (exact 0/1 product)
            int t = (row0 + arow) >> 11;  // S_DIM = 2048 rows per t
            const float* q = &g_qk[t * D_DIM + k0 + akoff];
            av.x *= q[0]; av.y *= q[1]; av.z *= q[2]; av.w *= q[3];
        }
        float4 bv = *(const float4*)&B[(k0 + bk) * D_DIM + col0 + bcol];

        __syncthreads();
        As[akoff + 0][arow] = make_float2(av.x, av.x);
        As[akoff + 1][arow] = make_float2(av.y, av.y);
        As[akoff + 2][arow] = make_float2(av.z, av.z);
        As[akoff + 3][arow] = make_float2(av.w, av.w);
        *(float4*)&Bs[bk][bcol] = bv;
        __syncthreads();

#pragma unroll
        for (int kk = 0; kk < 8; kk++) {
            ull a[8], b[4];
            {
                ulonglong2 v0 = *(const ulonglong2*)&As[kk][ta4];
                ulonglong2 v1 = *(const ulonglong2*)&As[kk][ta4 + 2];
                ulonglong2 v2 = *(const ulonglong2*)&As[kk][ta4 + 64];
                ulonglong2 v3 = *(const ulonglong2*)&As[kk][ta4 + 66];
                a[0] = v0.x; a[1] = v0.y; a[2] = v1.x; a[3] = v1.y;
                a[4] = v2.x; a[5] = v2.y; a[6] = v3.x; a[7] = v3.y;
            }
            {
                ulonglong2 w0 = *(const ulonglong2*)&Bs[kk][tc4];
                ulonglong2 w1 = *(const ulonglong2*)&Bs[kk][tc4 + 64];
                b[0] = w0.x; b[1] = w0.y; b[2] = w1.x; b[3] = w1.y;
            }
#pragma unroll
            for (int i = 0; i < 8; i++)
#pragma unroll
                for (int j = 0; j < 4; j++) fma2(acc[i][j], a[i], b[j]);
        }
    }

#pragma unroll
    for (int i = 0; i < 8; i++) {
        int r = row0 + ((i < 4) ? (ta4 + i) : (ta4 + 64 + (i - 4)));
#pragma unroll
        for (int j = 0; j < 4; j++) {
            int c = col0 + ((j < 2) ? (tc4 + 2 * j) : (tc4 + 64 + 2 * (j - 2)));
            *(float2*)&C[r * D_DIM + c] = *(float2*)&acc[i][j];
        }
    }
}

// ---------------------------------------------------------------------------
// K3: BatchNorm1d over (T,D) per channel s, then IF node over T. In-place.
// Scalar math matches XLA: correctly-rounded div by 3072, libdevice rsqrtf.
// grid = (S_DIM, 3) -> tensor 0/1/2 = Q/K/V
// ---------------------------------------------------------------------------
__global__ void k_bn_if() {
    const int s = blockIdx.x;
    float* X = (blockIdx.y == 0) ? g_q : ((blockIdx.y == 1) ? g_k : g_v);
    __shared__ float sm[T_DIM * D_DIM];  // 12 KB
    __shared__ float red[256];
    const int tid = threadIdx.x;

    float psum = 0.0f;
    for (int i = tid; i < T_DIM * D_DIM; i += 256) {
        int t = i / D_DIM, d = i - t * D_DIM;
        float val = X[t * SD + s * D_DIM + d];
        sm[i] = val;
        psum += val;
    }
    red[tid] = psum;
    __syncthreads();
    for (int off = 128; off; off >>= 1) {
        if (tid < off) red[tid] += red[tid + off];
        __syncthreads();
    }
    float mean = red[0] / 3072.0f;
    __syncthreads();

    float pv = 0.0f;
    for (int i = tid; i < T_DIM * D_DIM; i += 256) {
        float dv = sm[i] - mean;
        pv += dv * dv;
    }
    red[tid] = pv;
    __syncthreads();
    for (int off = 128; off; off >>= 1) {
        if (tid < off) red[tid] += red[tid + off];
        __syncthreads();
    }
    float var = red[0] / 3072.0f;
    float rs = rsqrtf(var + 1e-5f);

    for (int d = tid; d < D_DIM; d += 256) {
        float v = 0.0f;
#pragma unroll
        for (int t = 0; t < T_DIM; t++) {
            float val = (sm[t * D_DIM + d] - mean) * rs;
            v += val;
            float sp = (v >= 1.0f) ? 1.0f : 0.0f;
            X[t * SD + s * D_DIM + d] = sp;
            if (sp != 0.0f) v = 0.0f;
        }
    }
}

// ---------------------------------------------------------------------------
// K4a: QK counts — coalesced partial sums + float atomics. All partials are
// integers (binary products), so the result is EXACT and order-independent
// (fp32 adds of integers < 2^24 are exact) -> deterministic despite atomics.
// grid = (T_DIM * 3 [c-chunks of 256], 8 [s-chunks of 256]), 256 threads.
// ---------------------------------------------------------------------------
__global__ void k_qk_partial() {
    const int t = blockIdx.x / 3;
    const int c = (blockIdx.x % 3) * 256 + threadIdx.x;
    const int s0 = blockIdx.y * 256;
    const float* Qp = &g_q[t * SD + s0 * D_DIM + c];
    const float* Kp = &g_k[t * SD + s0 * D_DIM + c];
    float acc = 0.0f;
#pragma unroll 8
    for (int s = 0; s < 256; s++)
        acc += Qp[s * D_DIM] * Kp[s * D_DIM];
    atomicAdd(&g_qk_raw[t * D_DIM + c], acc);
}

// K4b: IF node over T on the exact integer counts -> talking-heads spikes.
__global__ void k_qk_fin() {
    int c = blockIdx.x * blockDim.x + threadIdx.x;
    if (c >= D_DIM) return;
    float v = 0.0f;
#pragma unroll
    for (int t = 0; t < T_DIM; t++) {
        v += g_qk_raw[t * D_DIM + c];
        float sp = (v >= 1.0f) ? 1.0f : 0.0f;
        g_qk[t * D_DIM + c] = sp;
        if (sp != 0.0f) v = 0.0f;
    }
}

// ---------------------------------------------------------------------------
// K7: final BatchNorm1d over (T,D) per channel s -> d_out.
// ---------------------------------------------------------------------------
__global__ void k_bn_out(float* __restrict__ out) {
    const int s = blockIdx.x;
    __shared__ float sm[T_DIM * D_DIM];
    __shared__ float red[256];
    const int tid = threadIdx.x;

    float psum = 0.0f;
    for (int i = tid; i < T_DIM * D_DIM; i += 256) {
        int t = i / D_DIM, d = i - t * D_DIM;
        float val = g_o[t * SD + s * D_DIM + d];
        sm[i] = val;
        psum += val;
    }
    red[tid] = psum;
    __syncthreads();
    for (int off = 128; off; off >>= 1) {
        if (tid < off) red[tid] += red[tid + off];
        __syncthreads();
    }
    float mean = red[0] / 3072.0f;
    __syncthreads();

    float pv = 0.0f;
    for (int i = tid; i < T_DIM * D_DIM; i += 256) {
        float dv = sm[i] - mean;
        pv += dv * dv;
    }
    red[tid] = pv;
    __syncthreads();
    for (int off = 128; off; off >>= 1) {
        if (tid < off) red[tid] += red[tid + off];
        __syncthreads();
    }
    float var = red[0] / 3072.0f;
    float rs = rsqrtf(var + 1e-5f);

    for (int i = tid; i < T_DIM * D_DIM; i += 256) {
        int t = i / D_DIM, d = i - t * D_DIM;
        out[t * SD + s * D_DIM + d] = (sm[i] - mean) * rs;
    }
}

// ---------------------------------------------------------------------------
// Launch: graph-capturable, allocation-free, deterministic.
// Inputs (metadata order): x, wq, wk, wv, wo, cur_pos(unused)
// ---------------------------------------------------------------------------
extern "C" void kernel_launch(void* const* d_in, const int* in_sizes, int n_in,
                              void* d_out, int out_size) {
    const float* x  = (const float*)d_in[0];
    const float* wq = (const float*)d_in[1];
    const float* wk = (const float*)d_in[2];
    const float* wv = (const float*)d_in[3];
    const float* wo = (const float*)d_in[4];
    float* out = (float*)d_out;

    // 0. zero QK accumulator (independent; launched first)
    k_zero_qk<<<(T_DIM * D_DIM + 255) / 256, 256>>>();

    // 1. init spikes
    k_init_spike<<<(SD + 255) / 256, 256>>>(x);

    // 2. Q/K/V projections (one fused GEMM launch, 3 weights)
    {
        dim3 grid(18, 64);
        k_gemm<0><<<grid, 256>>>(wq, wk, wv);
    }

    // 3. BN + IF for Q, K, V (in-place -> spikes)
    {
        dim3 grid(S_DIM, 3);
        k_bn_if<<<grid, 256>>>();
    }

    // 4. talking-heads QK reduction + IF
    {
        dim3 grid(T_DIM * 3, 8);
        k_qk_partial<<<grid, 256>>>();
        k_qk_fin<<<(D_DIM + 255) / 256, 256>>>();
    }

    // 5. final GEMM: (V_spike * QK) @ wo  (mask fused into A load)
    {
        dim3 grid(6, 64);
        k_gemm<1><<<grid, 256>>>(wo, wo, wo);
    }

    // 6. final BN -> output
    k_bn_out<<<S_DIM, 256>>>(out);
}

// round 7
// speedup vs baseline: 1.0032x; 1.0032x over previous
#include <cuda_runtime.h>
#include <cuda_bf16.h>

// Problem dims (fixed by the reference)
#define T_DIM 4
#define S_DIM 2048
#define D_DIM 768
#define SD (S_DIM * D_DIM)          // 1572864
#define TSD (T_DIM * SD)            // 6291456
#define N_HEADS 12
#define HEAD_DIM 64

typedef unsigned long long ull;

// Scratch (device globals: allocation-free)
__device__ float g_spk0[TSD];   // init spikes (0/1 as float)
__device__ float g_q[TSD];      // Q pre-BN, then Q spikes (in-place)
__device__ float g_k[TSD];      // K pre-BN, then K spikes (in-place)
__device__ float g_v[TSD];      // V pre-BN, then V spikes (in-place)
__device__ float g_o[TSD];      // final GEMM output pre-BN
__device__ float g_qk_raw[T_DIM * D_DIM];  // QK counts (exact integers)
__device__ float g_qk[T_DIM * D_DIM];      // talking-heads spikes (t, h*64+j)

__device__ __forceinline__ void fma2(ull &d, ull a, ull b) {
    asm("fma.rn.f32x2 %0, %1, %2, %0;" : "+l"(d) : "l"(a), "l"(b));
}

// ---------------------------------------------------------------------------
// K0: zero the QK accumulator (graph-safe, no memset API)
// ---------------------------------------------------------------------------
__global__ void k_zero_qk() {
    int i = blockIdx.x * blockDim.x + threadIdx.x;
    if (i < T_DIM * D_DIM) g_qk_raw[i] = 0.0f;
}

// ---------------------------------------------------------------------------
// K1: init_spike — IF node over T per (s,d). Exact elementwise fp32
// (bit-identical to the reference scan).
// ---------------------------------------------------------------------------
__global__ void k_init_spike(const float* __restrict__ x) {
    int idx = blockIdx.x * blockDim.x + threadIdx.x;
    if (idx >= SD) return;
    float v = 0.0f;
#pragma unroll
    for (int t = 0; t < T_DIM; t++) {
        v += x[t * SD + idx];
        float sp = (v >= 1.0f) ? 1.0f : 0.0f;
        g_spk0[t * SD + idx] = sp;
        if (sp != 0.0f) v = 0.0f;
    }
}

// ---------------------------------------------------------------------------
// GEMM: C(8192x768) = A(8192x768) @ B(768x768), fp32.
// Per-element accumulation: single accumulator, strictly ascending k, IEEE
// fma per step (fma.rn.f32x2 == two independent FFMAs) — the same chain a
// cuBLAS/Triton fp32 SIMT mainloop produces, maximizing bit-match odds.
// PHASE 0: A = g_spk0, three weights -> g_q / g_k / g_v (grid.x = 18)
// PHASE 1: A = g_v (V spikes) * g_qk mask (exact 0/1 product), B0=wo -> g_o
// Tile 128x128, BK=8, 256 threads, per-thread 8x8 via 32x fma.rn.f32x2.
// ---------------------------------------------------------------------------
template <int PHASE>
__global__ __launch_bounds__(256) void k_gemm(const float* __restrict__ B0,
                                              const float* __restrict__ B1,
                                              const float* __restrict__ B2) {
    __shared__ __align__(16) float2 As[8][128];  // A values duplicated (a,a)
    __shared__ __align__(16) float  Bs[8][128];

    const int tid = threadIdx.x;
    const float* A;
    const float* B;
    float* C;
    int col0;
    if (PHASE == 0) {
        int w = blockIdx.x / 6;
        col0 = (blockIdx.x % 6) * 128;
        A = g_spk0;
        B = (w == 0) ? B0 : ((w == 1) ? B1 : B2);
        C = (w == 0) ? g_q : ((w == 1) ? g_k : g_v);
    } else {
        col0 = blockIdx.x * 128;
        A = g_v;
        B = B0;
        C = g_o;
    }
    const int row0 = blockIdx.y * 128;

    // global-load mapping
    const int arow  = tid >> 1;          // 0..127
    const int akoff = (tid & 1) * 4;     // 0 or 4
    const int bk    = tid >> 5;          // 0..7
    const int bcol  = (tid & 31) * 4;    // 0..124

    // compute-fragment mapping (4 + 64-split for conflict-free LDS)
    const int ta4 = (tid >> 4) * 4;      // rows {ta4..+3, ta4+64..+67}
    const int tc4 = (tid & 15) * 4;      // cols {tc4..+3, tc4+64..+67}

    ull acc[8][4];
#pragma unroll
    for (int i = 0; i < 8; i++)
#pragma unroll
        for (int j = 0; j < 4; j++) acc[i][j] = 0ull;

    for (int k0 = 0; k0 < D_DIM; k0 += 8) {
        float4 av = *(const float4*)&A[(row0 + arow) * D_DIM + k0 + akoff];
        if (PHASE == 1) {
            // fuse QKV = V_spike * QK mask into the A load (exact 0/1 product)
            int t = (row0 + arow) >> 11;  // S_DIM = 2048 rows per t
            const float* q = &g_qk[t * D_DIM + k0 + akoff];
            av.x *= q[0]; av.y *= q[1]; av.z *= q[2]; av.w *= q[3];
        }
        float4 bv = *(const float4*)&B[(k0 + bk) * D_DIM + col0 + bcol];

        __syncthreads();
        As[akoff + 0][arow] = make_float2(av.x, av.x);
        As[akoff + 1][arow] = make_float2(av.y, av.y);
        As[akoff + 2][arow] = make_float2(av.z, av.z);
        As[akoff + 3][arow] = make_float2(av.w, av.w);
        *(float4*)&Bs[bk][bcol] = bv;
        __syncthreads();

#pragma unroll
        for (int kk = 0; kk < 8; kk++) {
            ull a[8], b[4];
            {
                ulonglong2 v0 = *(const ulonglong2*)&As[kk][ta4];
                ulonglong2 v1 = *(const ulonglong2*)&As[kk][ta4 + 2];
                ulonglong2 v2 = *(const ulonglong2*)&As[kk][ta4 + 64];
                ulonglong2 v3 = *(const ulonglong2*)&As[kk][ta4 + 66];
                a[0] = v0.x; a[1] = v0.y; a[2] = v1.x; a[3] = v1.y;
                a[4] = v2.x; a[5] = v2.y; a[6] = v3.x; a[7] = v3.y;
            }
            {
                ulonglong2 w0 = *(const ulonglong2*)&Bs[kk][tc4];
                ulonglong2 w1 = *(const ulonglong2*)&Bs[kk][tc4 + 64];
                b[0] = w0.x; b[1] = w0.y; b[2] = w1.x; b[3] = w1.y;
            }
#pragma unroll
            for (int i = 0; i < 8; i++)
#pragma unroll
                for (int j = 0; j < 4; j++) fma2(acc[i][j], a[i], b[j]);
        }
    }

#pragma unroll
    for (int i = 0; i < 8; i++) {
        int r = row0 + ((i < 4) ? (ta4 + i) : (ta4 + 64 + (i - 4)));
#pragma unroll
        for (int j = 0; j < 4; j++) {
            int c = col0 + ((j < 2) ? (tc4 + 2 * j) : (tc4 + 64 + 2 * (j - 2)));
            *(float2*)&C[r * D_DIM + c] = *(float2*)&acc[i][j];
        }
    }
}

// ---------------------------------------------------------------------------
// K3: BatchNorm1d over (T,D) per channel s, then IF node over T. In-place.
// Scalar math matches XLA: correctly-rounded div by 3072, libdevice rsqrtf.
// grid = (S_DIM, 3) -> tensor 0/1/2 = Q/K/V
// ---------------------------------------------------------------------------
__global__ void k_bn_if() {
    const int s = blockIdx.x;
    float* X = (blockIdx.y == 0) ? g_q : ((blockIdx.y == 1) ? g_k : g_v);
    __shared__ float sm[T_DIM * D_DIM];  // 12 KB
    __shared__ float red[256];
    const int tid = threadIdx.x;

    float psum = 0.0f;
    for (int i = tid; i < T_DIM * D_DIM; i += 256) {
        int t = i / D_DIM, d = i - t * D_DIM;
        float val = X[t * SD + s * D_DIM + d];
        sm[i] = val;
        psum += val;
    }
    red[tid] = psum;
    __syncthreads();
    for (int off = 128; off; off >>= 1) {
        if (tid < off) red[tid] += red[tid + off];
        __syncthreads();
    }
    float mean = red[0] / 3072.0f;
    __syncthreads();

    float pv = 0.0f;
    for (int i = tid; i < T_DIM * D_DIM; i += 256) {
        float dv = sm[i] - mean;
        pv += dv * dv;
    }
    red[tid] = pv;
    __syncthreads();
    for (int off = 128; off; off >>= 1) {
        if (tid < off) red[tid] += red[tid + off];
        __syncthreads();
    }
    float var = red[0] / 3072.0f;
    float rs = rsqrtf(var + 1e-5f);

    for (int d = tid; d < D_DIM; d += 256) {
        float v = 0.0f;
#pragma unroll
        for (int t = 0; t < T_DIM; t++) {
            float val = (sm[t * D_DIM + d] - mean) * rs;
            v += val;
            float sp = (v >= 1.0f) ? 1.0f : 0.0f;
            X[t * SD + s * D_DIM + d] = sp;
            if (sp != 0.0f) v = 0.0f;
        }
    }
}

// ---------------------------------------------------------------------------
// K4a: QK counts — coalesced partial sums + float atomics. All partials are
// integers (binary products), so the result is EXACT and order-independent
// (fp32 adds of integers < 2^24 are exact) -> deterministic despite atomics.
// grid = (T_DIM * 3 [c-chunks of 256], 8 [s-chunks of 256]), 256 threads.
// ---------------------------------------------------------------------------
__global__ void k_qk_partial() {
    const int t = blockIdx.x / 3;
    const int c = (blockIdx.x % 3) * 256 + threadIdx.x;
    const int s0 = blockIdx.y * 256;
    const float* Qp = &g_q[t * SD + s0 * D_DIM + c];
    const float* Kp = &g_k[t * SD + s0 * D_DIM + c];
    float acc = 0.0f;
#pragma unroll 8
    for (int s = 0; s < 256; s++)
        acc += Qp[s * D_DIM] * Kp[s * D_DIM];
    atomicAdd(&g_qk_raw[t * D_DIM + c], acc);
}

// K4b: IF node over T on the exact integer counts -> talking-heads spikes.
__global__ void k_qk_fin() {
    int c = blockIdx.x * blockDim.x + threadIdx.x;
    if (c >= D_DIM) return;
    float v = 0.0f;
#pragma unroll
    for (int t = 0; t < T_DIM; t++) {
        v += g_qk_raw[t * D_DIM + c];
        float sp = (v >= 1.0f) ? 1.0f : 0.0f;
        g_qk[t * D_DIM + c] = sp;
        if (sp != 0.0f) v = 0.0f;
    }
}

// ---------------------------------------------------------------------------
// K7: final BatchNorm1d over (T,D) per channel s -> d_out.
// ---------------------------------------------------------------------------
__global__ void k_bn_out(float* __restrict__ out) {
    const int s = blockIdx.x;
    __shared__ float sm[T_DIM * D_DIM];
    __shared__ float red[256];
    const int tid = threadIdx.x;

    float psum = 0.0f;
    for (int i = tid; i < T_DIM * D_DIM; i += 256) {
        int t = i / D_DIM, d = i - t * D_DIM;
        float val = g_o[t * SD + s * D_DIM + d];
        sm[i] = val;
        psum += val;
    }
    red[tid] = psum;
    __syncthreads();
    for (int off = 128; off; off >>= 1) {
        if (tid < off) red[tid] += red[tid + off];
        __syncthreads();
    }
    float mean = red[0] / 3072.0f;
    __syncthreads();

    float pv = 0.0f;
    for (int i = tid; i < T_DIM * D_DIM; i += 256) {
        float dv = sm[i] - mean;
        pv += dv * dv;
    }
    red[tid] = pv;
    __syncthreads();
    for (int off = 128; off; off >>= 1) {
        if (tid < off) red[tid] += red[tid + off];
        __syncthreads();
    }
    float var = red[0] / 3072.0f;
    float rs = rsqrtf(var + 1e-5f);

    for (int i = tid; i < T_DIM * D_DIM; i += 256) {
        int t = i / D_DIM, d = i - t * D_DIM;
        out[t * SD + s * D_DIM + d] = (sm[i] - mean) * rs;
    }
}

// ---------------------------------------------------------------------------
// Launch: graph-capturable, allocation-free, deterministic.
// Inputs (metadata order): x, wq, wk, wv, wo, cur_pos(unused)
// ---------------------------------------------------------------------------
extern "C" void kernel_launch(void* const* d_in, const int* in_sizes, int n_in,
                              void* d_out, int out_size) {
    const float* x  = (const float*)d_in[0];
    const float* wq = (const float*)d_in[1];
    const float* wk = (const float*)d_in[2];
    const float* wv = (const float*)d_in[3];
    const float* wo = (const float*)d_in[4];
    float* out = (float*)d_out;

    // 0. zero QK accumulator (independent; launched first)
    k_zero_qk<<<(T_DIM * D_DIM + 255) / 256, 256>>>();

    // 1. init spikes
    k_init_spike<<<(SD + 255) / 256, 256>>>(x);

    // 2. Q/K/V projections (one fused GEMM launch, 3 weights)
    {
        dim3 grid(18, 64);
        k_gemm<0><<<grid, 256>>>(wq, wk, wv);
    }

    // 3. BN + IF for Q, K, V (in-place -> spikes)
    {
        dim3 grid(S_DIM, 3);
        k_bn_if<<<grid, 256>>>();
    }

    // 4. talking-heads QK reduction + IF
    {
        dim3 grid(T_DIM * 3, 8);
        k_qk_partial<<<grid, 256>>>();
        k_qk_fin<<<(D_DIM + 255) / 256, 256>>>();
    }

    // 5. final GEMM: (V_spike * QK) @ wo  (mask fused into A load)
    {
        dim3 grid(6, 64);
        k_gemm<1><<<grid, 256>>>(wo, wo, wo);
    }

    // 6. final BN -> output
    k_bn_out<<<S_DIM, 256>>>(out);
}

// round 8
// speedup vs baseline: 1.0046x; 1.0014x over previous
#include <cuda_runtime.h>
#include <cuda_bf16.h>

// Problem dims (fixed by the reference)
#define T_DIM 4
#define S_DIM 2048
#define D_DIM 768
#define SD (S_DIM * D_DIM)          // 1572864
#define TSD (T_DIM * SD)            // 6291456
#define N_HEADS 12
#define HEAD_DIM 64

typedef unsigned long long ull;

// Scratch (device globals: allocation-free)
__device__ float g_spk0[TSD];   // init spikes (0/1 as float)
__device__ float g_q[TSD];      // Q pre-BN, then Q spikes (in-place)
__device__ float g_k[TSD];      // K pre-BN, then K spikes (in-place)
__device__ float g_v[TSD];      // V pre-BN, then V spikes (in-place)
__device__ float g_o[TSD];      // final GEMM output pre-BN
__device__ float g_qk_raw[T_DIM * D_DIM];  // QK counts (exact integers)
__device__ float g_qk[T_DIM * D_DIM];      // talking-heads spikes (t, h*64+j)

__device__ __forceinline__ void fma2(ull &d, ull a, ull b) {
    asm("fma.rn.f32x2 %0, %1, %2, %0;" : "+l"(d) : "l"(a), "l"(b));
}

// ---------------------------------------------------------------------------
// K0: zero the QK accumulator (graph-safe, no memset API)
// ---------------------------------------------------------------------------
__global__ void k_zero_qk() {
    int i = blockIdx.x * blockDim.x + threadIdx.x;
    if (i < T_DIM * D_DIM) g_qk_raw[i] = 0.0f;
}

// ---------------------------------------------------------------------------
// K1: init_spike — IF node over T per (s,d). Exact elementwise fp32
// (bit-identical to the reference scan).
// ---------------------------------------------------------------------------
__global__ void k_init_spike(const float* __restrict__ x) {
    int idx = blockIdx.x * blockDim.x + threadIdx.x;
    if (idx >= SD) return;
    float v = 0.0f;
#pragma unroll
    for (int t = 0; t < T_DIM; t++) {
        v += x[t * SD + idx];
        float sp = (v >= 1.0f) ? 1.0f : 0.0f;
        g_spk0[t * SD + idx] = sp;
        if (sp != 0.0f) v = 0.0f;
    }
}

// ---------------------------------------------------------------------------
// GEMM: C(8192x768) = A(8192x768) @ B(768x768), fp32.
// Per-element accumulation: single accumulator, strictly ascending k, IEEE
// fma per step (fma.rn.f32x2 == two independent FFMAs) — the same chain a
// cuBLAS/Triton fp32 SIMT mainloop produces, maximizing bit-match odds.
// PHASE 0: A = g_spk0, three weights -> g_q / g_k / g_v (grid.x = 18)
// PHASE 1: A = g_v (V spikes) * g_qk mask (exact 0/1 product), B0=wo -> g_o
// Tile 128x128, BK=8, 256 threads, per-thread 8x8 via 32x fma.rn.f32x2.
// ---------------------------------------------------------------------------
template <int PHASE>
__global__ __launch_bounds__(256) void k_gemm(const float* __restrict__ B0,
                                              const float* __restrict__ B1,
                                              const float* __restrict__ B2) {
    __shared__ __align__(16) float2 As[8][128];  // A values duplicated (a,a)
    __shared__ __align__(16) float  Bs[8][128];

    const int tid = threadIdx.x;
    const float* A;
    const float* B;
    float* C;
    int col0;
    if (PHASE == 0) {
        int w = blockIdx.x / 6;
        col0 = (blockIdx.x % 6) * 128;
        A = g_spk0;
        B = (w == 0) ? B0 : ((w == 1) ? B1 : B2);
        C = (w == 0) ? g_q : ((w == 1) ? g_k : g_v);
    } else {
        col0 = blockIdx.x * 128;
        A = g_v;
        B = B0;
        C = g_o;
    }
    const int row0 = blockIdx.y * 128;

    // global-load mapping
    const int arow  = tid >> 1;          // 0..127
    const int akoff = (tid & 1) * 4;     // 0 or 4
    const int bk    = tid >> 5;          // 0..7
    const int bcol  = (tid & 31) * 4;    // 0..124

    // compute-fragment mapping (4 + 64-split for conflict-free LDS)
    const int ta4 = (tid >> 4) * 4;      // rows {ta4..+3, ta4+64..+67}
    const int tc4 = (tid & 15) * 4;      // cols {tc4..+3, tc4+64..+67}

    ull acc[8][4];
#pragma unroll
    for (int i = 0; i < 8; i++)
#pragma unroll
        for (int j = 0; j < 4; j++) acc[i][j] = 0ull;

    for (int k0 = 0; k0 < D_DIM; k0 += 8) {
        float4 av = *(const float4*)&A[(row0 + arow) * D_DIM + k0 + akoff];
        if (PHASE == 1) {
            // fuse QKV = V_spike * QK mask into the A load (exact 0/1 product)
            int t = (row0 + arow) >> 11;  // S_DIM = 2048 rows per t
            const float* q = &g_qk[t * D_DIM + k0 + akoff];
            av.x *= q[0]; av.y *= q[1]; av.z *= q[2]; av.w *= q[3];
        }
        float4 bv = *(const float4*)&B[(k0 + bk) * D_DIM + col0 + bcol];

        __syncthreads();
        As[akoff + 0][arow] = make_float2(av.x, av.x);
        As[akoff + 1][arow] = make_float2(av.y, av.y);
        As[akoff + 2][arow] = make_float2(av.z, av.z);
        As[akoff + 3][arow] = make_float2(av.w, av.w);
        *(float4*)&Bs[bk][bcol] = bv;
        __syncthreads();

#pragma unroll
        for (int kk = 0; kk < 8; kk++) {
            ull a[8], b[4];
            {
                ulonglong2 v0 = *(const ulonglong2*)&As[kk][ta4];
                ulonglong2 v1 = *(const ulonglong2*)&As[kk][ta4 + 2];
                ulonglong2 v2 = *(const ulonglong2*)&As[kk][ta4 + 64];
                ulonglong2 v3 = *(const ulonglong2*)&As[kk][ta4 + 66];
                a[0] = v0.x; a[1] = v0.y; a[2] = v1.x; a[3] = v1.y;
                a[4] = v2.x; a[5] = v2.y; a[6] = v3.x; a[7] = v3.y;
            }
            {
                ulonglong2 w0 = *(const ulonglong2*)&Bs[kk][tc4];
                ulonglong2 w1 = *(const ulonglong2*)&Bs[kk][tc4 + 64];
                b[0] = w0.x; b[1] = w0.y; b[2] = w1.x; b[3] = w1.y;
            }
#pragma unroll
            for (int i = 0; i < 8; i++)
#pragma unroll
                for (int j = 0; j < 4; j++) fma2(acc[i][j], a[i], b[j]);
        }
    }

#pragma unroll
    for (int i = 0; i < 8; i++) {
        int r = row0 + ((i < 4) ? (ta4 + i) : (ta4 + 64 + (i - 4)));
#pragma unroll
        for (int j = 0; j < 4; j++) {
            int c = col0 + ((j < 2) ? (tc4 + 2 * j) : (tc4 + 64 + 2 * (j - 2)));
            *(float2*)&C[r * D_DIM + c] = *(float2*)&acc[i][j];
        }
    }
}

// ---------------------------------------------------------------------------
// K3: BatchNorm1d over (T,D) per channel s, then IF node over T. In-place.
// Scalar math matches XLA: correctly-rounded div by 3072, libdevice rsqrtf.
// grid = (S_DIM, 3) -> tensor 0/1/2 = Q/K/V
// ---------------------------------------------------------------------------
__global__ void k_bn_if() {
    const int s = blockIdx.x;
    float* X = (blockIdx.y == 0) ? g_q : ((blockIdx.y == 1) ? g_k : g_v);
    __shared__ float sm[T_DIM * D_DIM];  // 12 KB
    __shared__ float red[256];
    const int tid = threadIdx.x;

    float psum = 0.0f;
    for (int i = tid; i < T_DIM * D_DIM; i += 256) {
        int t = i / D_DIM, d = i - t * D_DIM;
        float val = X[t * SD + s * D_DIM + d];
        sm[i] = val;
        psum += val;
    }
    red[tid] = psum;
    __syncthreads();
    for (int off = 128; off; off >>= 1) {
        if (tid < off) red[tid] += red[tid + off];
        __syncthreads();
    }
    float mean = red[0] / 3072.0f;
    __syncthreads();

    float pv = 0.0f;
    for (int i = tid; i < T_DIM * D_DIM; i += 256) {
        float dv = sm[i] - mean;
        pv += dv * dv;
    }
    red[tid] = pv;
    __syncthreads();
    for (int off = 128; off; off >>= 1) {
        if (tid < off) red[tid] += red[tid + off];
        __syncthreads();
    }
    float var = red[0] / 3072.0f;
    float rs = rsqrtf(var + 1e-5f);

    for (int d = tid; d < D_DIM; d += 256) {
        float v = 0.0f;
#pragma unroll
        for (int t = 0; t < T_DIM; t++) {
            float val = (sm[t * D_DIM + d] - mean) * rs;
            v += val;
            float sp = (v >= 1.0f) ? 1.0f : 0.0f;
            X[t * SD + s * D_DIM + d] = sp;
            if (sp != 0.0f) v = 0.0f;
        }
    }
}

// ---------------------------------------------------------------------------
// K4a: QK counts — coalesced partial sums + float atomics. All partials are
// integers (binary products), so the result is EXACT and order-independent
// (fp32 adds of integers < 2^24 are exact) -> deterministic despite atomics.
// grid = (T_DIM * 3 [c-chunks of 256], 8 [s-chunks of 256]), 256 threads.
// ---------------------------------------------------------------------------
__global__ void k_qk_partial() {
    const int t = blockIdx.x / 3;
    const int c = (blockIdx.x % 3) * 256 + threadIdx.x;
    const int s0 = blockIdx.y * 256;
    const float* Qp = &g_q[t * SD + s0 * D_DIM + c];
    const float* Kp = &g_k[t * SD + s0 * D_DIM + c];
    float acc = 0.0f;
#pragma unroll 8
    for (int s = 0; s < 256; s++)
        acc += Qp[s * D_DIM] * Kp[s * D_DIM];
    atomicAdd(&g_qk_raw[t * D_DIM + c], acc);
}

// K4b: IF node over T on the exact integer counts -> talking-heads spikes.
__global__ void k_qk_fin() {
    int c = blockIdx.x * blockDim.x + threadIdx.x;
    if (c >= D_DIM) return;
    float v = 0.0f;
#pragma unroll
    for (int t = 0; t < T_DIM; t++) {
        v += g_qk_raw[t * D_DIM + c];
        float sp = (v >= 1.0f) ? 1.0f : 0.0f;
        g_qk[t * D_DIM + c] = sp;
        if (sp != 0.0f) v = 0.0f;
    }
}

// ---------------------------------------------------------------------------
// K7: final BatchNorm1d over (T,D) per channel s -> d_out.
// ---------------------------------------------------------------------------
__global__ void k_bn_out(float* __restrict__ out) {
    const int s = blockIdx.x;
    __shared__ float sm[T_DIM * D_DIM];
    __shared__ float red[256];
    const int tid = threadIdx.x;

    float psum = 0.0f;
    for (int i = tid; i < T_DIM * D_DIM; i += 256) {
        int t = i / D_DIM, d = i - t * D_DIM;
        float val = g_o[t * SD + s * D_DIM + d];
        sm[i] = val;
        psum += val;
    }
    red[tid] = psum;
    __syncthreads();
    for (int off = 128; off; off >>= 1) {
        if (tid < off) red[tid] += red[tid + off];
        __syncthreads();
    }
    float mean = red[0] / 3072.0f;
    __syncthreads();

    float pv = 0.0f;
    for (int i = tid; i < T_DIM * D_DIM; i += 256) {
        float dv = sm[i] - mean;
        pv += dv * dv;
    }
    red[tid] = pv;
    __syncthreads();
    for (int off = 128; off; off >>= 1) {
        if (tid < off) red[tid] += red[tid + off];
        __syncthreads();
    }
    float var = red[0] / 3072.0f;
    float rs = rsqrtf(var + 1e-5f);

    for (int i = tid; i < T_DIM * D_DIM; i += 256) {
        int t = i / D_DIM, d = i - t * D_DIM;
        out[t * SD + s * D_DIM + d] = (sm[i] - mean) * rs;
    }
}

// ---------------------------------------------------------------------------
// Launch: graph-capturable, allocation-free, deterministic.
// Inputs (metadata order): x, wq, wk, wv, wo, cur_pos(unused)
// ---------------------------------------------------------------------------
extern "C" void kernel_launch(void* const* d_in, const int* in_sizes, int n_in,
                              void* d_out, int out_size) {
    const float* x  = (const float*)d_in[0];
    const float* wq = (const float*)d_in[1];
    const float* wk = (const float*)d_in[2];
    const float* wv = (const float*)d_in[3];
    const float* wo = (const float*)d_in[4];
    float* out = (float*)d_out;

    // 0. zero QK accumulator (independent; launched first)
    k_zero_qk<<<(T_DIM * D_DIM + 255) / 256, 256>>>();

    // 1. init spikes
    k_init_spike<<<(SD + 255) / 256, 256>>>(x);

    // 2. Q/K/V projections (one fused GEMM launch, 3 weights)
    {
        dim3 grid(18, 64);
        k_gemm<0><<<grid, 256>>>(wq, wk, wv);
    }

    // 3. BN + IF for Q, K, V (in-place -> spikes)
    {
        dim3 grid(S_DIM, 3);
        k_bn_if<<<grid, 256>>>();
    }

    // 4. talking-heads QK reduction + IF
    {
        dim3 grid(T_DIM * 3, 8);
        k_qk_partial<<<grid, 256>>>();
        k_qk_fin<<<(D_DIM + 255) / 256, 256>>>();
    }

    // 5. final GEMM: (V_spike * QK) @ wo  (mask fused into A load)
    {
        dim3 grid(6, 64);
        k_gemm<1><<<grid, 256>>>(wo, wo, wo);
    }

    // 6. final BN -> output
    k_bn_out<<<S_DIM, 256>>>(out);
}

// round 13
// speedup vs baseline: 1.8415x; 1.8331x over previous
#include <cuda_runtime.h>
#include <cuda_bf16.h>
#include <cstdint>

#define T_DIM 4
#define S_DIM 2048
#define D_DIM 768
#define SD (S_DIM * D_DIM)
#define TSD (T_DIM * SD)
#define DD (D_DIM * D_DIM)

// ---- device scratch (allocation-free) ----
__device__ __nv_bfloat16 g_spk0[TSD];          // init spikes (exact 0/1)
__device__ float g_q[TSD], g_k[TSD], g_v[TSD], g_o[TSD];   // pre-BN fp32
__device__ __nv_bfloat16 g_qs[TSD], g_ks[TSD], g_vs[TSD];  // spikes bf16
__device__ float g_qk_raw[T_DIM * D_DIM];
__device__ __nv_bfloat16 g_qkm[T_DIM * D_DIM];
__device__ __nv_bfloat16 g_wqt[DD], g_wkt[DD]; // transposed [n][k] bf16
__device__ __nv_bfloat16 g_wvt[3 * DD];        // V: hi/lo/lo2 planes
__device__ __nv_bfloat16 g_wot[2 * DD];        // O: hi/lo planes

#define SWZ128(o) ((o) ^ (((o) >> 3) & 0x70))

__device__ __forceinline__ uint32_t smem_u32(const void* p) {
    uint32_t a;
    asm("{ .reg .u64 t; cvta.to.shared.u64 t, %1; cvt.u32.u64 %0, t; }"
        : "=r"(a) : "l"(p));
    return a;
}
__device__ __forceinline__ void cp16(uint32_t dst, const void* src) {
    asm volatile("cp.async.cg.shared.global [%0], [%1], 16;" :: "r"(dst), "l"(src));
}
__device__ __forceinline__ void cp_commit() {
    asm volatile("cp.async.commit_group;" ::: "memory");
}
__device__ __forceinline__ void ldm_x4(uint32_t addr, uint32_t& r0, uint32_t& r1,
                                       uint32_t& r2, uint32_t& r3) {
    asm volatile("ldmatrix.sync.aligned.m8n8.x4.shared.b16 {%0,%1,%2,%3}, [%4];"
                 : "=r"(r0), "=r"(r1), "=r"(r2), "=r"(r3) : "r"(addr));
}
__device__ __forceinline__ void mma16816(float* c, const uint32_t* a,
                                         uint32_t b0, uint32_t b1) {
    asm volatile(
        "mma.sync.aligned.m16n8k16.row.col.f32.bf16.bf16.f32 "
        "{%0,%1,%2,%3}, {%4,%5,%6,%7}, {%8,%9}, {%0,%1,%2,%3};"
        : "+f"(c[0]), "+f"(c[1]), "+f"(c[2]), "+f"(c[3])
        : "r"(a[0]), "r"(a[1]), "r"(a[2]), "r"(a[3]), "r"(b0), "r"(b1));
}

// ---- weight prep: transpose + bf16 split ----
__global__ void k_prep(const float* __restrict__ wq, const float* __restrict__ wk,
                       const float* __restrict__ wv, const float* __restrict__ wo) {
    __shared__ float tile[32][33];
    const int z = blockIdx.z;
    const float* W = (z == 0) ? wq : (z == 1) ? wk : (z == 2) ? wv : wo;
    const int k0 = blockIdx.x * 32, n0 = blockIdx.y * 32;
    const int tx = threadIdx.x, ty = threadIdx.y;
    for (int i = ty; i < 32; i += 8) tile[i][tx] = W[(k0 + i) * D_DIM + n0 + tx];
    __syncthreads();
    for (int i = ty; i < 32; i += 8) {
        int n = n0 + i, k = k0 + tx;
        float w = tile[tx][i];
        __nv_bfloat16 hi = __float2bfloat16(w);
        if (z == 0) g_wqt[n * D_DIM + k] = hi;
        else if (z == 1) g_wkt[n * D_DIM + k] = hi;
        else {
            float r1 = w - __bfloat162float(hi);
            __nv_bfloat16 lo = __float2bfloat16(r1);
            if (z == 2) {
                g_wvt[n * D_DIM + k] = hi;
                g_wvt[DD + n * D_DIM + k] = lo;
                g_wvt[2 * DD + n * D_DIM + k] =
                    __float2bfloat16(r1 - __bfloat162float(lo));
            } else {
                g_wot[n * D_DIM + k] = hi;
                g_wot[DD + n * D_DIM + k] = lo;
            }
        }
    }
}

__global__ void k_zero_qk() {
    int i = blockIdx.x * blockDim.x + threadIdx.x;
    if (i < T_DIM * D_DIM) g_qk_raw[i] = 0.0f;
}

__global__ void k_init_spike(const float* __restrict__ x) {
    int idx = blockIdx.x * blockDim.x + threadIdx.x;
    if (idx >= SD) return;
    float v = 0.0f;
#pragma unroll
    for (int t = 0; t < T_DIM; t++) {
        v += x[t * SD + idx];
        float sp = (v >= 1.0f) ? 1.0f : 0.0f;
        g_spk0[t * SD + idx] = __float2bfloat16(sp);
        if (sp != 0.0f) v = 0.0f;
    }
}

// ---------------------------------------------------------------------------
// GEMM via mma.sync bf16 (sm_80 baseline ISA -> compiles for plain sm_103).
// C[8192,768](fp32) = A[8192,768](bf16) @ B^T, B stored [n][k] bf16.
// CTA tile 128x128, BK=64, 8 warps (2m x 4n), warp tile 64x32.
// TERMS B-planes accumulate into the same accumulators (weight splitting).
// PASS 0: z=0 Q, z=1 K (TERMS=1). PASS 2: V (3). PASS 3: O (2, A pre-masked).
// SMEM: A 2x16KB double-buffered; B 2xTERMSx16KB. SW128 swizzle, ldmatrix.
// ---------------------------------------------------------------------------
template <int PASS>
__global__ __launch_bounds__(256) void k_mma() {
    extern __shared__ __align__(16) char smp[];
    const uint32_t smp_u = smem_u32(smp);

    constexpr int TERMS = (PASS == 2) ? 3 : (PASS == 3) ? 2 : 1;
    const int tid = threadIdx.x, wid = tid >> 5, lane = tid & 31;
    const int wm = wid & 1, wn = wid >> 1;          // warp tile (64m x 32n)
    const int n0 = blockIdx.x * 128, m0 = blockIdx.y * 128;

    const __nv_bfloat16* A;
    const __nv_bfloat16* B;
    float* C;
    if (PASS == 0) {
        A = g_spk0;
        B = (blockIdx.z == 0) ? g_wqt : g_wkt;
        C = (blockIdx.z == 0) ? g_q : g_k;
    } else if (PASS == 2) {
        A = g_spk0; B = g_wvt; C = g_v;
    } else {
        A = g_vs; B = g_wot; C = g_o;
    }

    // smem offsets
    auto A_off = [&](int st) { return (uint32_t)(st * 16384); };
    auto B_off = [&](int st, int term) {
        return (uint32_t)(32768 + (st * TERMS + term) * 16384);
    };

    auto fillA = [&](int chunk, int st) {
        const int k0 = chunk * 64;
#pragma unroll
        for (int c = 0; c < 4; c++) {
            int idx = tid + c * 256;
            int r = idx >> 3, cc = idx & 7;
            cp16(smp_u + A_off(st) + SWZ128((uint32_t)(r * 128 + cc * 16)),
                 &A[(m0 + r) * D_DIM + k0 + cc * 8]);
        }
    };
    auto fillB = [&](int chunk, int st) {
        const int k0 = chunk * 64;
        for (int term = 0; term < TERMS; term++) {
            const __nv_bfloat16* Bp = B + term * DD;
#pragma unroll
            for (int c = 0; c < 4; c++) {
                int idx = tid + c * 256;
                int r = idx >> 3, cc = idx & 7;
                cp16(smp_u + B_off(st, term) + SWZ128((uint32_t)(r * 128 + cc * 16)),
                     &Bp[(n0 + r) * D_DIM + k0 + cc * 8]);
            }
        }
    };

    float acc[4][4][4];   // [mf][nf][4]
#pragma unroll
    for (int i = 0; i < 4; i++)
#pragma unroll
        for (int j = 0; j < 4; j++)
#pragma unroll
            for (int e = 0; e < 4; e++) acc[i][j][e] = 0.0f;

    fillA(0, 0); fillB(0, 0); cp_commit();

    const int lrow = lane & 15, lsel = lane >> 4;   // ldmatrix lane mapping

    for (int i = 0; i < 12; i++) {
        const int st = i & 1;
        if (i + 1 < 12) {
            fillA(i + 1, st ^ 1); fillB(i + 1, st ^ 1); cp_commit();
            asm volatile("cp.async.wait_group 1;" ::: "memory");
        } else {
            asm volatile("cp.async.wait_group 0;" ::: "memory");
        }
        __syncthreads();

#pragma unroll
        for (int kk = 0; kk < 4; kk++) {
            // A fragments: 4 x m16, k16 slice kk
            uint32_t a[4][4];
#pragma unroll
            for (int mf = 0; mf < 4; mf++) {
                uint32_t row = (uint32_t)(wm * 64 + mf * 16 + lrow);
                uint32_t addr = smp_u + A_off(st) +
                                SWZ128(row * 128 + (uint32_t)(kk * 2 + lsel) * 16);
                ldm_x4(addr, a[mf][0], a[mf][1], a[mf][2], a[mf][3]);
            }
            for (int term = 0; term < TERMS; term++) {
#pragma unroll
                for (int bh = 0; bh < 2; bh++) {
                    uint32_t row = (uint32_t)(wn * 32 + bh * 16 + lrow);
                    uint32_t addr = smp_u + B_off(st, term) +
                                    SWZ128(row * 128 + (uint32_t)(kk * 2 + lsel) * 16);
                    uint32_t b0, b1, b2, b3;
                    ldm_x4(addr, b0, b1, b2, b3);
                    // nf = bh*2: frag {b0,b2}; nf = bh*2+1: frag {b1,b3}
#pragma unroll
                    for (int mf = 0; mf < 4; mf++) {
                        mma16816(acc[mf][bh * 2 + 0], a[mf], b0, b2);
                        mma16816(acc[mf][bh * 2 + 1], a[mf], b1, b3);
                    }
                }
            }
        }
        __syncthreads();
    }

    // epilogue
#pragma unroll
    for (int mf = 0; mf < 4; mf++) {
        int r0 = m0 + wm * 64 + mf * 16 + (lane >> 2);
#pragma unroll
        for (int nf = 0; nf < 4; nf++) {
            int cc = n0 + wn * 32 + nf * 8 + (lane & 3) * 2;
            *(float2*)&C[r0 * D_DIM + cc] = make_float2(acc[mf][nf][0], acc[mf][nf][1]);
            *(float2*)&C[(r0 + 8) * D_DIM + cc] = make_float2(acc[mf][nf][2], acc[mf][nf][3]);
        }
    }
}

// ---- BN + IF per channel s (grid (2048,3)); V: near-threshold exact recompute ----
__global__ __launch_bounds__(256) void k_bn_if(const float* __restrict__ wv) {
    const int s = blockIdx.x, y = blockIdx.y, tid = threadIdx.x;
    const int lane = tid & 31, wrp = tid >> 5;
    const float* X = (y == 0) ? g_q : (y == 1) ? g_k : g_v;
    __nv_bfloat16* O = (y == 0) ? g_qs : (y == 1) ? g_ks : g_vs;
    const int base = s * D_DIM + tid;
    __shared__ float part[8];

    float vals[12];
#pragma unroll
    for (int t = 0; t < T_DIM; t++)
#pragma unroll
        for (int j = 0; j < 3; j++) vals[t * 3 + j] = X[t * SD + base + j * 256];

    float lsum = 0.0f;
#pragma unroll
    for (int i = 0; i < 12; i++) lsum += vals[i];
#pragma unroll
    for (int o = 16; o; o >>= 1) lsum += __shfl_xor_sync(~0u, lsum, o);
    if (lane == 0) part[wrp] = lsum;
    __syncthreads();
    float tot = 0.0f;
#pragma unroll
    for (int w = 0; w < 8; w++) tot += part[w];
    const float mean = tot / 3072.0f;

    float lv = 0.0f;
#pragma unroll
    for (int i = 0; i < 12; i++) { float d = vals[i] - mean; lv += d * d; }
#pragma unroll
    for (int o = 16; o; o >>= 1) lv += __shfl_xor_sync(~0u, lv, o);
    __syncthreads();
    if (lane == 0) part[wrp] = lv;
    __syncthreads();
    float vtot = 0.0f;
#pragma unroll
    for (int w = 0; w < 8; w++) vtot += part[w];
    const float rs = rsqrtf(vtot / 3072.0f + 1e-5f);

#pragma unroll
    for (int j = 0; j < 3; j++) {
        const int d = tid + j * 256;
        float v = 0.0f, sp4[4];
        bool flag = false;
#pragma unroll
        for (int t = 0; t < T_DIM; t++) {
            float val = (vals[t * 3 + j] - mean) * rs;
            v += val;
            if (fabsf(v - 1.0f) < 3e-4f) flag = true;
            float sp = (v >= 1.0f) ? 1.0f : 0.0f;
            sp4[t] = sp;
            if (sp != 0.0f) v = 0.0f;
        }
        if (y == 2 && flag) {
            // exact ascending-k fp32 fma chain (matches reference GEMM order)
            float ex[4] = {0.0f, 0.0f, 0.0f, 0.0f};
            const __nv_bfloat16* sp0 = &g_spk0[s * D_DIM];
            for (int k = 0; k < D_DIM; k++) {
                float w = wv[k * D_DIM + d];
#pragma unroll
                for (int t = 0; t < T_DIM; t++)
                    ex[t] = fmaf(__bfloat162float(sp0[t * SD + k]), w, ex[t]);
            }
            v = 0.0f;
#pragma unroll
            for (int t = 0; t < T_DIM; t++) {
                float val = (ex[t] - mean) * rs;
                v += val;
                float sp = (v >= 1.0f) ? 1.0f : 0.0f;
                sp4[t] = sp;
                if (sp != 0.0f) v = 0.0f;
            }
        }
#pragma unroll
        for (int t = 0; t < T_DIM; t++)
            O[t * SD + base + j * 256] = __float2bfloat16(sp4[t]);
    }
}

// ---- QK counts (exact integer float atomics) + IF ----
__global__ void k_qk_partial() {
    const int t = blockIdx.x / 3;
    const int c = (blockIdx.x % 3) * 256 + threadIdx.x;
    const int s0 = blockIdx.y * 256;
    const __nv_bfloat16* Qp = &g_qs[t * SD + s0 * D_DIM + c];
    const __nv_bfloat16* Kp = &g_ks[t * SD + s0 * D_DIM + c];
    float acc = 0.0f;
#pragma unroll 8
    for (int s = 0; s < 256; s++)
        acc += __bfloat162float(Qp[s * D_DIM]) * __bfloat162float(Kp[s * D_DIM]);
    atomicAdd(&g_qk_raw[t * D_DIM + c], acc);
}
__global__ void k_qk_fin() {
    int c = blockIdx.x * blockDim.x + threadIdx.x;
    if (c >= D_DIM) return;
    float v = 0.0f;
#pragma unroll
    for (int t = 0; t < T_DIM; t++) {
        v += g_qk_raw[t * D_DIM + c];
        float sp = (v >= 1.0f) ? 1.0f : 0.0f;
        g_qkm[t * D_DIM + c] = __float2bfloat16(sp);
        if (sp != 0.0f) v = 0.0f;
    }
}

// ---- pre-mask V spikes with talking-heads mask (exact 0/1 product) ----
__global__ void k_mask_v() {
    const int s = blockIdx.x, tid = threadIdx.x;
#pragma unroll
    for (int j = 0; j < 3; j++) {
        int d = tid + j * 256;
#pragma unroll
        for (int t = 0; t < T_DIM; t++) {
            int off = t * SD + s * D_DIM + d;
            float m = __bfloat162float(g_qkm[t * D_DIM + d]);
            g_vs[off] = __float2bfloat16(__bfloat162float(g_vs[off]) * m);
        }
    }
}

// ---- final BN -> out ----
__global__ void k_bn_out(float* __restrict__ out) {
    const int s = blockIdx.x, tid = threadIdx.x;
    const int lane = tid & 31, wrp = tid >> 5;
    __shared__ float part[8];
    const int base = s * D_DIM + tid;

    float vals[12];
#pragma unroll
    for (int t = 0; t < T_DIM; t++)
#pragma unroll
        for (int j = 0; j < 3; j++) vals[t * 3 + j] = g_o[t * SD + base + j * 256];

    float lsum = 0.0f;
#pragma unroll
    for (int i = 0; i < 12; i++) lsum += vals[i];
#pragma unroll
    for (int o = 16; o; o >>= 1) lsum += __shfl_xor_sync(~0u, lsum, o);
    if (lane == 0) part[wrp] = lsum;
    __syncthreads();
    float tot = 0.0f;
#pragma unroll
    for (int w = 0; w < 8; w++) tot += part[w];
    const float mean = tot / 3072.0f;

    float lv = 0.0f;
#pragma unroll
    for (int i = 0; i < 12; i++) { float d = vals[i] - mean; lv += d * d; }
#pragma unroll
    for (int o = 16; o; o >>= 1) lv += __shfl_xor_sync(~0u, lv, o);
    __syncthreads();
    if (lane == 0) part[wrp] = lv;
    __syncthreads();
    float vtot = 0.0f;
#pragma unroll
    for (int w = 0; w < 8; w++) vtot += part[w];
    const float rs = rsqrtf(vtot / 3072.0f + 1e-5f);

#pragma unroll
    for (int t = 0; t < T_DIM; t++)
#pragma unroll
        for (int j = 0; j < 3; j++)
            out[t * SD + base + j * 256] = (vals[t * 3 + j] - mean) * rs;
}

// ---- launch ----
extern "C" void kernel_launch(void* const* d_in, const int* in_sizes, int n_in,
                              void* d_out, int out_size) {
    const float* x  = (const float*)d_in[0];
    const float* wq = (const float*)d_in[1];
    const float* wk = (const float*)d_in[2];
    const float* wv = (const float*)d_in[3];
    const float* wo = (const float*)d_in[4];
    float* out = (float*)d_out;

    // smem: A 2x16KB + B 2xTERMSx16KB
    cudaFuncSetAttribute(k_mma<0>, cudaFuncAttributeMaxDynamicSharedMemorySize, 65536);
    cudaFuncSetAttribute(k_mma<2>, cudaFuncAttributeMaxDynamicSharedMemorySize, 131072);
    cudaFuncSetAttribute(k_mma<3>, cudaFuncAttributeMaxDynamicSharedMemorySize, 98304);

    k_prep<<<dim3(24, 24, 4), dim3(32, 8)>>>(wq, wk, wv, wo);
    k_zero_qk<<<(T_DIM * D_DIM + 255) / 256, 256>>>();
    k_init_spike<<<(SD + 255) / 256, 256>>>(x);

    k_mma<0><<<dim3(6, 64, 2), 256, 65536>>>();    // Q, K
    k_mma<2><<<dim3(6, 64, 1), 256, 131072>>>();   // V (triple split)

    k_bn_if<<<dim3(S_DIM, 3), 256>>>(wv);

    k_qk_partial<<<dim3(12, 8), 256>>>();
    k_qk_fin<<<(D_DIM + 255) / 256, 256>>>();
    k_mask_v<<<S_DIM, 256>>>();

    k_mma<3><<<dim3(6, 64, 1), 256, 98304>>>();    // O (double split, masked A)

    k_bn_out<<<S_DIM, 256>>>(out);
}

// round 14
// speedup vs baseline: 1.8627x; 1.0115x over previous
#include <cuda_runtime.h>
#include <cuda_bf16.h>
#include <cstdint>

#define T_DIM 4
#define S_DIM 2048
#define D_DIM 768
#define SD (S_DIM * D_DIM)
#define TSD (T_DIM * SD)
#define DD (D_DIM * D_DIM)

// ---- device scratch (allocation-free) ----
__device__ __nv_bfloat16 g_spk0[TSD];          // init spikes (exact 0/1)
__device__ float g_q[TSD], g_k[TSD], g_v[TSD], g_o[TSD];   // pre-BN fp32
__device__ __nv_bfloat16 g_qs[TSD], g_ks[TSD], g_vs[TSD];  // spikes bf16
__device__ float g_qk_raw[T_DIM * D_DIM];
__device__ __nv_bfloat16 g_qkm[T_DIM * D_DIM];
__device__ __nv_bfloat16 g_wqt[DD], g_wkt[DD]; // transposed [n][k] bf16
__device__ __nv_bfloat16 g_wvt[3 * DD];        // V: hi/lo/lo2 planes
__device__ __nv_bfloat16 g_wot[2 * DD];        // O: hi/lo planes

#define SWZ128(o) ((o) ^ (((o) >> 3) & 0x70))

__device__ __forceinline__ uint32_t smem_u32(const void* p) {
    uint32_t a;
    asm("{ .reg .u64 t; cvta.to.shared.u64 t, %1; cvt.u32.u64 %0, t; }"
        : "=r"(a) : "l"(p));
    return a;
}
__device__ __forceinline__ void cp16(uint32_t dst, const void* src) {
    asm volatile("cp.async.cg.shared.global [%0], [%1], 16;" :: "r"(dst), "l"(src));
}
__device__ __forceinline__ void cp_commit() {
    asm volatile("cp.async.commit_group;" ::: "memory");
}
__device__ __forceinline__ void ldm_x4(uint32_t addr, uint32_t& r0, uint32_t& r1,
                                       uint32_t& r2, uint32_t& r3) {
    asm volatile("ldmatrix.sync.aligned.m8n8.x4.shared.b16 {%0,%1,%2,%3}, [%4];"
                 : "=r"(r0), "=r"(r1), "=r"(r2), "=r"(r3) : "r"(addr));
}
__device__ __forceinline__ void mma16816(float* c, const uint32_t* a,
                                         uint32_t b0, uint32_t b1) {
    asm volatile(
        "mma.sync.aligned.m16n8k16.row.col.f32.bf16.bf16.f32 "
        "{%0,%1,%2,%3}, {%4,%5,%6,%7}, {%8,%9}, {%0,%1,%2,%3};"
        : "+f"(c[0]), "+f"(c[1]), "+f"(c[2]), "+f"(c[3])
        : "r"(a[0]), "r"(a[1]), "r"(a[2]), "r"(a[3]), "r"(b0), "r"(b1));
}

// ---- weight prep: transpose + bf16 split ----
__global__ void k_prep(const float* __restrict__ wq, const float* __restrict__ wk,
                       const float* __restrict__ wv, const float* __restrict__ wo) {
    __shared__ float tile[32][33];
    const int z = blockIdx.z;
    const float* W = (z == 0) ? wq : (z == 1) ? wk : (z == 2) ? wv : wo;
    const int k0 = blockIdx.x * 32, n0 = blockIdx.y * 32;
    const int tx = threadIdx.x, ty = threadIdx.y;
    for (int i = ty; i < 32; i += 8) tile[i][tx] = W[(k0 + i) * D_DIM + n0 + tx];
    __syncthreads();
    for (int i = ty; i < 32; i += 8) {
        int n = n0 + i, k = k0 + tx;
        float w = tile[tx][i];
        __nv_bfloat16 hi = __float2bfloat16(w);
        if (z == 0) g_wqt[n * D_DIM + k] = hi;
        else if (z == 1) g_wkt[n * D_DIM + k] = hi;
        else {
            float r1 = w - __bfloat162float(hi);
            __nv_bfloat16 lo = __float2bfloat16(r1);
            if (z == 2) {
                g_wvt[n * D_DIM + k] = hi;
                g_wvt[DD + n * D_DIM + k] = lo;
                g_wvt[2 * DD + n * D_DIM + k] =
                    __float2bfloat16(r1 - __bfloat162float(lo));
            } else {
                g_wot[n * D_DIM + k] = hi;
                g_wot[DD + n * D_DIM + k] = lo;
            }
        }
    }
}

// init spikes + zero QK accumulator (merged)
__global__ void k_init_spike(const float* __restrict__ x) {
    int idx = blockIdx.x * blockDim.x + threadIdx.x;
    if (idx < T_DIM * D_DIM) g_qk_raw[idx] = 0.0f;
    if (idx >= SD) return;
    float v = 0.0f;
#pragma unroll
    for (int t = 0; t < T_DIM; t++) {
        v += x[t * SD + idx];
        float sp = (v >= 1.0f) ? 1.0f : 0.0f;
        g_spk0[t * SD + idx] = __float2bfloat16(sp);
        if (sp != 0.0f) v = 0.0f;
    }
}

// ---------------------------------------------------------------------------
// GEMM via mma.sync bf16. CTA 128x128, BK=64, 8 warps (2m x 4n), warp 64x32.
// 3-stage cp.async pipeline + register double-buffered ldmatrix fragments.
// PASS 0: z=0 Q, z=1 K (TERMS=1). PASS 2: V (3 planes). PASS 3: O (2 planes,
// QK mask fused into A fill — exact 0/1 bf16 product).
// ---------------------------------------------------------------------------
template <int PASS>
__global__ __launch_bounds__(256) void k_mma() {
    extern __shared__ __align__(16) char smp[];
    const uint32_t smp_u = smem_u32(smp);

    constexpr int TERMS = (PASS == 2) ? 3 : (PASS == 3) ? 2 : 1;
    constexpr int NCH = 12;
    const int tid = threadIdx.x, wid = tid >> 5, lane = tid & 31;
    const int wm = wid & 1, wn = wid >> 1;          // warp tile (64m x 32n)
    const int n0 = blockIdx.x * 128, m0 = blockIdx.y * 128;
    const int t_idx = m0 >> 11;

    const __nv_bfloat16* A;
    const __nv_bfloat16* B;
    float* C;
    if (PASS == 0) {
        A = g_spk0;
        B = (blockIdx.z == 0) ? g_wqt : g_wkt;
        C = (blockIdx.z == 0) ? g_q : g_k;
    } else if (PASS == 2) {
        A = g_spk0; B = g_wvt; C = g_v;
    } else {
        A = g_vs; B = g_wot; C = g_o;
    }

    auto A_off = [&](int st) { return (uint32_t)(st * 16384); };
    auto B_off = [&](int st, int term) {
        return (uint32_t)(49152 + (st * TERMS + term) * 16384);
    };

    auto fillA = [&](int chunk, int st) {
        const int k0 = chunk * 64;
#pragma unroll
        for (int c = 0; c < 4; c++) {
            int idx = tid + c * 256;
            int r = idx >> 3, cc = idx & 7;
            if (PASS == 3) {
                // fused QK mask (exact 0/1 product), synchronous store
                uint4 v = *(const uint4*)&A[(m0 + r) * D_DIM + k0 + cc * 8];
                uint4 mv = *(const uint4*)&g_qkm[t_idx * D_DIM + k0 + cc * 8];
                __nv_bfloat162* vv = (__nv_bfloat162*)&v;
                const __nv_bfloat162* mm = (const __nv_bfloat162*)&mv;
                vv[0] = __hmul2(vv[0], mm[0]); vv[1] = __hmul2(vv[1], mm[1]);
                vv[2] = __hmul2(vv[2], mm[2]); vv[3] = __hmul2(vv[3], mm[3]);
                *(uint4*)(smp + A_off(st) + SWZ128((uint32_t)(r * 128 + cc * 16))) = v;
            } else {
                cp16(smp_u + A_off(st) + SWZ128((uint32_t)(r * 128 + cc * 16)),
                     &A[(m0 + r) * D_DIM + k0 + cc * 8]);
            }
        }
    };
    auto fillB = [&](int chunk, int st) {
        const int k0 = chunk * 64;
        for (int term = 0; term < TERMS; term++) {
            const __nv_bfloat16* Bp = B + term * DD;
#pragma unroll
            for (int c = 0; c < 4; c++) {
                int idx = tid + c * 256;
                int r = idx >> 3, cc = idx & 7;
                cp16(smp_u + B_off(st, term) + SWZ128((uint32_t)(r * 128 + cc * 16)),
                     &Bp[(n0 + r) * D_DIM + k0 + cc * 8]);
            }
        }
    };

    float acc[4][4][4];
#pragma unroll
    for (int i = 0; i < 4; i++)
#pragma unroll
        for (int j = 0; j < 4; j++)
#pragma unroll
            for (int e = 0; e < 4; e++) acc[i][j][e] = 0.0f;

    const int lrow = lane & 15, lsel = lane >> 4;

    // prologue: stages 0,1
    fillA(0, 0); fillB(0, 0); cp_commit();
    fillA(1, 1); fillB(1, 1); cp_commit();

    uint32_t afr[2][4][4], bfr[2][2][4];

    for (int i = 0; i < NCH; i++) {
        const int st = i % 3;
        if (i + 2 < NCH) {
            const int st2 = (i + 2) % 3;
            fillA(i + 2, st2); fillB(i + 2, st2); cp_commit();
            asm volatile("cp.async.wait_group 2;" ::: "memory");
        } else if (i + 1 < NCH) {
            asm volatile("cp.async.wait_group 1;" ::: "memory");
        } else {
            asm volatile("cp.async.wait_group 0;" ::: "memory");
        }
        __syncthreads();

        // ---- compute chunk (register double-buffered fragments) ----
        auto ldA = [&](int buf, int kk) {
#pragma unroll
            for (int mf = 0; mf < 4; mf++) {
                uint32_t row = (uint32_t)(wm * 64 + mf * 16 + lrow);
                uint32_t addr = smp_u + A_off(st) +
                                SWZ128(row * 128 + (uint32_t)(kk * 2 + lsel) * 16);
                ldm_x4(addr, afr[buf][mf][0], afr[buf][mf][1],
                       afr[buf][mf][2], afr[buf][mf][3]);
            }
        };
        auto ldB = [&](int buf, int kk, int term) {
#pragma unroll
            for (int bh = 0; bh < 2; bh++) {
                uint32_t row = (uint32_t)(wn * 32 + bh * 16 + lrow);
                uint32_t addr = smp_u + B_off(st, term) +
                                SWZ128(row * 128 + (uint32_t)(kk * 2 + lsel) * 16);
                ldm_x4(addr, bfr[buf][bh][0], bfr[buf][bh][1],
                       bfr[buf][bh][2], bfr[buf][bh][3]);
            }
        };

        ldA(0, 0); ldB(0, 0, 0);
#pragma unroll
        for (int kk = 0; kk < 4; kk++) {
#pragma unroll
            for (int term = 0; term < TERMS; term++) {
                const int cur = (kk * TERMS + term) & 1;
                const int nxt = cur ^ 1;
                if (term + 1 < TERMS) ldB(nxt, kk, term + 1);
                else if (kk + 1 < 4) ldB(nxt, kk + 1, 0);
                if (term == TERMS - 1 && kk + 1 < 4) ldA((kk + 1) & 1, kk + 1);
                const int ab = kk & 1;
#pragma unroll
                for (int bh = 0; bh < 2; bh++)
#pragma unroll
                    for (int mf = 0; mf < 4; mf++) {
                        mma16816(acc[mf][bh * 2 + 0], afr[ab][mf],
                                 bfr[cur][bh][0], bfr[cur][bh][2]);
                        mma16816(acc[mf][bh * 2 + 1], afr[ab][mf],
                                 bfr[cur][bh][1], bfr[cur][bh][3]);
                    }
            }
        }
        __syncthreads();
    }

    // epilogue
#pragma unroll
    for (int mf = 0; mf < 4; mf++) {
        int r0 = m0 + wm * 64 + mf * 16 + (lane >> 2);
#pragma unroll
        for (int nf = 0; nf < 4; nf++) {
            int cc = n0 + wn * 32 + nf * 8 + (lane & 3) * 2;
            *(float2*)&C[r0 * D_DIM + cc] = make_float2(acc[mf][nf][0], acc[mf][nf][1]);
            *(float2*)&C[(r0 + 8) * D_DIM + cc] = make_float2(acc[mf][nf][2], acc[mf][nf][3]);
        }
    }
}

// ---- BN + IF per channel s (grid (2048,3)); V: near-threshold exact recompute ----
__global__ __launch_bounds__(256) void k_bn_if(const float* __restrict__ wv) {
    const int s = blockIdx.x, y = blockIdx.y, tid = threadIdx.x;
    const int lane = tid & 31, wrp = tid >> 5;
    const float* X = (y == 0) ? g_q : (y == 1) ? g_k : g_v;
    __nv_bfloat16* O = (y == 0) ? g_qs : (y == 1) ? g_ks : g_vs;
    const int base = s * D_DIM + tid;
    __shared__ float part[8];

    float vals[12];
#pragma unroll
    for (int t = 0; t < T_DIM; t++)
#pragma unroll
        for (int j = 0; j < 3; j++) vals[t * 3 + j] = X[t * SD + base + j * 256];

    float lsum = 0.0f;
#pragma unroll
    for (int i = 0; i < 12; i++) lsum += vals[i];
#pragma unroll
    for (int o = 16; o; o >>= 1) lsum += __shfl_xor_sync(~0u, lsum, o);
    if (lane == 0) part[wrp] = lsum;
    __syncthreads();
    float tot = 0.0f;
#pragma unroll
    for (int w = 0; w < 8; w++) tot += part[w];
    const float mean = tot / 3072.0f;

    float lv = 0.0f;
#pragma unroll
    for (int i = 0; i < 12; i++) { float d = vals[i] - mean; lv += d * d; }
#pragma unroll
    for (int o = 16; o; o >>= 1) lv += __shfl_xor_sync(~0u, lv, o);
    __syncthreads();
    if (lane == 0) part[wrp] = lv;
    __syncthreads();
    float vtot = 0.0f;
#pragma unroll
    for (int w = 0; w < 8; w++) vtot += part[w];
    const float rs = rsqrtf(vtot / 3072.0f + 1e-5f);

#pragma unroll
    for (int j = 0; j < 3; j++) {
        const int d = tid + j * 256;
        float v = 0.0f, sp4[4];
        bool flag = false;
#pragma unroll
        for (int t = 0; t < T_DIM; t++) {
            float val = (vals[t * 3 + j] - mean) * rs;
            v += val;
            if (fabsf(v - 1.0f) < 3e-4f) flag = true;
            float sp = (v >= 1.0f) ? 1.0f : 0.0f;
            sp4[t] = sp;
            if (sp != 0.0f) v = 0.0f;
        }
        if (y == 2 && flag) {
            // exact ascending-k fp32 fma chain (matches reference GEMM order)
            float ex[4] = {0.0f, 0.0f, 0.0f, 0.0f};
            const __nv_bfloat16* sp0 = &g_spk0[s * D_DIM];
            for (int k = 0; k < D_DIM; k++) {
                float w = wv[k * D_DIM + d];
#pragma unroll
                for (int t = 0; t < T_DIM; t++)
                    ex[t] = fmaf(__bfloat162float(sp0[t * SD + k]), w, ex[t]);
            }
            v = 0.0f;
#pragma unroll
            for (int t = 0; t < T_DIM; t++) {
                float val = (ex[t] - mean) * rs;
                v += val;
                float sp = (v >= 1.0f) ? 1.0f : 0.0f;
                sp4[t] = sp;
                if (sp != 0.0f) v = 0.0f;
            }
        }
#pragma unroll
        for (int t = 0; t < T_DIM; t++)
            O[t * SD + base + j * 256] = __float2bfloat16(sp4[t]);
    }
}

// ---- QK counts (exact integer float atomics) + IF ----
__global__ void k_qk_partial() {
    const int t = blockIdx.x / 3;
    const int c = (blockIdx.x % 3) * 256 + threadIdx.x;
    const int s0 = blockIdx.y * 256;
    const __nv_bfloat16* Qp = &g_qs[t * SD + s0 * D_DIM + c];
    const __nv_bfloat16* Kp = &g_ks[t * SD + s0 * D_DIM + c];
    float acc = 0.0f;
#pragma unroll 8
    for (int s = 0; s < 256; s++)
        acc += __bfloat162float(Qp[s * D_DIM]) * __bfloat162float(Kp[s * D_DIM]);
    atomicAdd(&g_qk_raw[t * D_DIM + c], acc);
}
__global__ void k_qk_fin() {
    int c = blockIdx.x * blockDim.x + threadIdx.x;
    if (c >= D_DIM) return;
    float v = 0.0f;
#pragma unroll
    for (int t = 0; t < T_DIM; t++) {
        v += g_qk_raw[t * D_DIM + c];
        float sp = (v >= 1.0f) ? 1.0f : 0.0f;
        g_qkm[t * D_DIM + c] = __float2bfloat16(sp);
        if (sp != 0.0f) v = 0.0f;
    }
}

// ---- final BN -> out ----
__global__ void k_bn_out(float* __restrict__ out) {
    const int s = blockIdx.x, tid = threadIdx.x;
    const int lane = tid & 31, wrp = tid >> 5;
    __shared__ float part[8];
    const int base = s * D_DIM + tid;

    float vals[12];
#pragma unroll
    for (int t = 0; t < T_DIM; t++)
#pragma unroll
        for (int j = 0; j < 3; j++) vals[t * 3 + j] = g_o[t * SD + base + j * 256];

    float lsum = 0.0f;
#pragma unroll
    for (int i = 0; i < 12; i++) lsum += vals[i];
#pragma unroll
    for (int o = 16; o; o >>= 1) lsum += __shfl_xor_sync(~0u, lsum, o);
    if (lane == 0) part[wrp] = lsum;
    __syncthreads();
    float tot = 0.0f;
#pragma unroll
    for (int w = 0; w < 8; w++) tot += part[w];
    const float mean = tot / 3072.0f;

    float lv = 0.0f;
#pragma unroll
    for (int i = 0; i < 12; i++) { float d = vals[i] - mean; lv += d * d; }
#pragma unroll
    for (int o = 16; o; o >>= 1) lv += __shfl_xor_sync(~0u, lv, o);
    __syncthreads();
    if (lane == 0) part[wrp] = lv;
    __syncthreads();
    float vtot = 0.0f;
#pragma unroll
    for (int w = 0; w < 8; w++) vtot += part[w];
    const float rs = rsqrtf(vtot / 3072.0f + 1e-5f);

#pragma unroll
    for (int t = 0; t < T_DIM; t++)
#pragma unroll
        for (int j = 0; j < 3; j++)
            out[t * SD + base + j * 256] = (vals[t * 3 + j] - mean) * rs;
}

// ---- launch ----
extern "C" void kernel_launch(void* const* d_in, const int* in_sizes, int n_in,
                              void* d_out, int out_size) {
    const float* x  = (const float*)d_in[0];
    const float* wq = (const float*)d_in[1];
    const float* wk = (const float*)d_in[2];
    const float* wv = (const float*)d_in[3];
    const float* wo = (const float*)d_in[4];
    float* out = (float*)d_out;

    // smem: A 3x16KB + B 3xTERMSx16KB
    cudaFuncSetAttribute(k_mma<0>, cudaFuncAttributeMaxDynamicSharedMemorySize, 98304);
    cudaFuncSetAttribute(k_mma<2>, cudaFuncAttributeMaxDynamicSharedMemorySize, 196608);
    cudaFuncSetAttribute(k_mma<3>, cudaFuncAttributeMaxDynamicSharedMemorySize, 147456);

    k_prep<<<dim3(24, 24, 4), dim3(32, 8)>>>(wq, wk, wv, wo);
    k_init_spike<<<(SD + 255) / 256, 256>>>(x);

    k_mma<0><<<dim3(6, 64, 2), 256, 98304>>>();    // Q, K
    k_mma<2><<<dim3(6, 64, 1), 256, 196608>>>();   // V (triple split)

    k_bn_if<<<dim3(S_DIM, 3), 256>>>(wv);

    k_qk_partial<<<dim3(12, 8), 256>>>();
    k_qk_fin<<<(D_DIM + 255) / 256, 256>>>();

    k_mma<3><<<dim3(6, 64, 1), 256, 147456>>>();   // O (double split, mask fused)

    k_bn_out<<<S_DIM, 256>>>(out);
}

// round 15
// speedup vs baseline: 1.9463x; 1.0449x over previous
#include <cuda_runtime.h>
#include <cuda_bf16.h>
#include <cstdint>

#define T_DIM 4
#define S_DIM 2048
#define D_DIM 768
#define SD (S_DIM * D_DIM)
#define TSD (T_DIM * SD)
#define DD (D_DIM * D_DIM)

// ---- device scratch (allocation-free) ----
__device__ __nv_bfloat16 g_spk0[TSD];          // init spikes (exact 0/1)
__device__ float g_v[TSD], g_o[TSD];           // pre-BN fp32 (V, O critical)
__device__ __nv_bfloat16 g_qs[TSD], g_ks[TSD]; // Q/K pre-BN bf16, then spikes (in-place)
__device__ __nv_bfloat16 g_vs[TSD];            // V spikes bf16
__device__ float g_qk_raw[T_DIM * D_DIM];
__device__ __nv_bfloat16 g_qkm[T_DIM * D_DIM];
__device__ __nv_bfloat16 g_wqt[DD], g_wkt[DD]; // transposed [n][k] bf16
__device__ __nv_bfloat16 g_wvt[3 * DD];        // V: hi/lo/lo2 planes
__device__ __nv_bfloat16 g_wot[2 * DD];        // O: hi/lo planes

#define SWZ128(o) ((o) ^ (((o) >> 3) & 0x70))

__device__ __forceinline__ uint32_t smem_u32(const void* p) {
    uint32_t a;
    asm("{ .reg .u64 t; cvta.to.shared.u64 t, %1; cvt.u32.u64 %0, t; }"
        : "=r"(a) : "l"(p));
    return a;
}
__device__ __forceinline__ void cp16(uint32_t dst, const void* src) {
    asm volatile("cp.async.cg.shared.global [%0], [%1], 16;" :: "r"(dst), "l"(src));
}
__device__ __forceinline__ void cp_commit() {
    asm volatile("cp.async.commit_group;" ::: "memory");
}
__device__ __forceinline__ void ldm_x4(uint32_t addr, uint32_t& r0, uint32_t& r1,
                                       uint32_t& r2, uint32_t& r3) {
    asm volatile("ldmatrix.sync.aligned.m8n8.x4.shared.b16 {%0,%1,%2,%3}, [%4];"
                 : "=r"(r0), "=r"(r1), "=r"(r2), "=r"(r3) : "r"(addr));
}
__device__ __forceinline__ void mma16816(float* c, const uint32_t* a,
                                         uint32_t b0, uint32_t b1) {
    asm volatile(
        "mma.sync.aligned.m16n8k16.row.col.f32.bf16.bf16.f32 "
        "{%0,%1,%2,%3}, {%4,%5,%6,%7}, {%8,%9}, {%0,%1,%2,%3};"
        : "+f"(c[0]), "+f"(c[1]), "+f"(c[2]), "+f"(c[3])
        : "r"(a[0]), "r"(a[1]), "r"(a[2]), "r"(a[3]), "r"(b0), "r"(b1));
}

// ---- weight prep: transpose + bf16 split ----
__global__ void k_prep(const float* __restrict__ wq, const float* __restrict__ wk,
                       const float* __restrict__ wv, const float* __restrict__ wo) {
    __shared__ float tile[32][33];
    const int z = blockIdx.z;
    const float* W = (z == 0) ? wq : (z == 1) ? wk : (z == 2) ? wv : wo;
    const int k0 = blockIdx.x * 32, n0 = blockIdx.y * 32;
    const int tx = threadIdx.x, ty = threadIdx.y;
    for (int i = ty; i < 32; i += 8) tile[i][tx] = W[(k0 + i) * D_DIM + n0 + tx];
    __syncthreads();
    for (int i = ty; i < 32; i += 8) {
        int n = n0 + i, k = k0 + tx;
        float w = tile[tx][i];
        __nv_bfloat16 hi = __float2bfloat16(w);
        if (z == 0) g_wqt[n * D_DIM + k] = hi;
        else if (z == 1) g_wkt[n * D_DIM + k] = hi;
        else {
            float r1 = w - __bfloat162float(hi);
            __nv_bfloat16 lo = __float2bfloat16(r1);
            if (z == 2) {
                g_wvt[n * D_DIM + k] = hi;
                g_wvt[DD + n * D_DIM + k] = lo;
                g_wvt[2 * DD + n * D_DIM + k] =
                    __float2bfloat16(r1 - __bfloat162float(lo));
            } else {
                g_wot[n * D_DIM + k] = hi;
                g_wot[DD + n * D_DIM + k] = lo;
            }
        }
    }
}

// init spikes + zero QK accumulator (merged)
__global__ void k_init_spike(const float* __restrict__ x) {
    int idx = blockIdx.x * blockDim.x + threadIdx.x;
    if (idx < T_DIM * D_DIM) g_qk_raw[idx] = 0.0f;
    if (idx >= SD) return;
    float v = 0.0f;
#pragma unroll
    for (int t = 0; t < T_DIM; t++) {
        v += x[t * SD + idx];
        float sp = (v >= 1.0f) ? 1.0f : 0.0f;
        g_spk0[t * SD + idx] = __float2bfloat16(sp);
        if (sp != 0.0f) v = 0.0f;
    }
}

// ---------------------------------------------------------------------------
// GEMM via mma.sync bf16. CTA 64x128, BK=64, 8 warps (2m x 4n), warp 32x32.
// 2 CTAs/SM (launch_bounds 256,2). Multi-stage cp.async + reg double-buffer.
// PASS 0: z=0 Q, z=1 K (TERMS=1, bf16 out). PASS 2: V (3 planes, fp32 out).
// PASS 3: O (2 planes, QK mask fused into A fill, fp32 out).
// SMEM: A NSTAGE x 8KB; B NSTAGE x TERMS x 16KB. SW128 swizzle, ldmatrix.
// ---------------------------------------------------------------------------
template <int PASS>
__global__ __launch_bounds__(256, 2) void k_mma() {
    extern __shared__ __align__(16) char smp[];
    const uint32_t smp_u = smem_u32(smp);

    constexpr int TERMS = (PASS == 2) ? 3 : (PASS == 3) ? 2 : 1;
    constexpr int NSTAGE = (TERMS == 1) ? 3 : 2;
    constexpr int NCH = 12;
    const int tid = threadIdx.x, wid = tid >> 5, lane = tid & 31;
    const int wm = wid & 1, wn = wid >> 1;          // warp tile (32m x 32n)
    const int n0 = blockIdx.x * 128, m0 = blockIdx.y * 64;
    const int t_idx = m0 >> 11;

    const __nv_bfloat16* A;
    const __nv_bfloat16* B;
    if (PASS == 0) {
        A = g_spk0;
        B = (blockIdx.z == 0) ? g_wqt : g_wkt;
    } else if (PASS == 2) {
        A = g_spk0; B = g_wvt;
    } else {
        A = g_vs; B = g_wot;
    }

    auto A_off = [&](int st) { return (uint32_t)(st * 8192); };
    auto B_off = [&](int st, int term) {
        return (uint32_t)(NSTAGE * 8192 + (st * TERMS + term) * 16384);
    };

    auto fillA = [&](int chunk, int st) {
        const int k0 = chunk * 64;
#pragma unroll
        for (int c = 0; c < 2; c++) {
            int idx = tid + c * 256;
            int r = idx >> 3, cc = idx & 7;
            if (PASS == 3) {
                uint4 v = *(const uint4*)&A[(m0 + r) * D_DIM + k0 + cc * 8];
                uint4 mv = *(const uint4*)&g_qkm[t_idx * D_DIM + k0 + cc * 8];
                __nv_bfloat162* vv = (__nv_bfloat162*)&v;
                const __nv_bfloat162* mm = (const __nv_bfloat162*)&mv;
                vv[0] = __hmul2(vv[0], mm[0]); vv[1] = __hmul2(vv[1], mm[1]);
                vv[2] = __hmul2(vv[2], mm[2]); vv[3] = __hmul2(vv[3], mm[3]);
                *(uint4*)(smp + A_off(st) + SWZ128((uint32_t)(r * 128 + cc * 16))) = v;
            } else {
                cp16(smp_u + A_off(st) + SWZ128((uint32_t)(r * 128 + cc * 16)),
                     &A[(m0 + r) * D_DIM + k0 + cc * 8]);
            }
        }
    };
    auto fillB = [&](int chunk, int st) {
        const int k0 = chunk * 64;
        for (int term = 0; term < TERMS; term++) {
            const __nv_bfloat16* Bp = B + term * DD;
#pragma unroll
            for (int c = 0; c < 4; c++) {
                int idx = tid + c * 256;
                int r = idx >> 3, cc = idx & 7;
                cp16(smp_u + B_off(st, term) + SWZ128((uint32_t)(r * 128 + cc * 16)),
                     &Bp[(n0 + r) * D_DIM + k0 + cc * 8]);
            }
        }
    };

    float acc[2][4][4];
#pragma unroll
    for (int i = 0; i < 2; i++)
#pragma unroll
        for (int j = 0; j < 4; j++)
#pragma unroll
            for (int e = 0; e < 4; e++) acc[i][j][e] = 0.0f;

    const int lrow = lane & 15, lsel = lane >> 4;

    // prologue: NSTAGE-1 stages in flight
#pragma unroll
    for (int s = 0; s < NSTAGE - 1; s++) {
        fillA(s, s); fillB(s, s); cp_commit();
    }

    uint32_t afr[2][2][4], bfr[2][2][4];

    for (int i = 0; i < NCH; i++) {
        const int st = i % NSTAGE;
        if (NSTAGE == 3) {
            if (i + 2 < NCH) {
                fillA(i + 2, (i + 2) % 3); fillB(i + 2, (i + 2) % 3); cp_commit();
                asm volatile("cp.async.wait_group 2;" ::: "memory");
            } else if (i + 1 < NCH) {
                asm volatile("cp.async.wait_group 1;" ::: "memory");
            } else {
                asm volatile("cp.async.wait_group 0;" ::: "memory");
            }
        } else {
            if (i + 1 < NCH) {
                fillA(i + 1, (i + 1) & 1); fillB(i + 1, (i + 1) & 1); cp_commit();
                asm volatile("cp.async.wait_group 1;" ::: "memory");
            } else {
                asm volatile("cp.async.wait_group 0;" ::: "memory");
            }
        }
        __syncthreads();

        auto ldA = [&](int buf, int kk) {
#pragma unroll
            for (int mf = 0; mf < 2; mf++) {
                uint32_t row = (uint32_t)(wm * 32 + mf * 16 + lrow);
                uint32_t addr = smp_u + A_off(st) +
                                SWZ128(row * 128 + (uint32_t)(kk * 2 + lsel) * 16);
                ldm_x4(addr, afr[buf][mf][0], afr[buf][mf][1],
                       afr[buf][mf][2], afr[buf][mf][3]);
            }
        };
        auto ldB = [&](int buf, int kk, int term) {
#pragma unroll
            for (int bh = 0; bh < 2; bh++) {
                uint32_t row = (uint32_t)(wn * 32 + bh * 16 + lrow);
                uint32_t addr = smp_u + B_off(st, term) +
                                SWZ128(row * 128 + (uint32_t)(kk * 2 + lsel) * 16);
                ldm_x4(addr, bfr[buf][bh][0], bfr[buf][bh][1],
                       bfr[buf][bh][2], bfr[buf][bh][3]);
            }
        };

        ldA(0, 0); ldB(0, 0, 0);
#pragma unroll
        for (int kk = 0; kk < 4; kk++) {
#pragma unroll
            for (int term = 0; term < TERMS; term++) {
                const int cur = (kk * TERMS + term) & 1;
                const int nxt = cur ^ 1;
                if (term + 1 < TERMS) ldB(nxt, kk, term + 1);
                else if (kk + 1 < 4) ldB(nxt, kk + 1, 0);
                if (term == TERMS - 1 && kk + 1 < 4) ldA((kk + 1) & 1, kk + 1);
                const int ab = kk & 1;
#pragma unroll
                for (int bh = 0; bh < 2; bh++)
#pragma unroll
                    for (int mf = 0; mf < 2; mf++) {
                        mma16816(acc[mf][bh * 2 + 0], afr[ab][mf],
                                 bfr[cur][bh][0], bfr[cur][bh][2]);
                        mma16816(acc[mf][bh * 2 + 1], afr[ab][mf],
                                 bfr[cur][bh][1], bfr[cur][bh][3]);
                    }
            }
        }
        __syncthreads();
    }

    // epilogue
#pragma unroll
    for (int mf = 0; mf < 2; mf++) {
        int r0 = m0 + wm * 32 + mf * 16 + (lane >> 2);
#pragma unroll
        for (int nf = 0; nf < 4; nf++) {
            int cc = n0 + wn * 32 + nf * 8 + (lane & 3) * 2;
            if (PASS == 0) {
                __nv_bfloat16* Cb = (blockIdx.z == 0) ? g_qs : g_ks;
                *(__nv_bfloat162*)&Cb[r0 * D_DIM + cc] =
                    __floats2bfloat162_rn(acc[mf][nf][0], acc[mf][nf][1]);
                *(__nv_bfloat162*)&Cb[(r0 + 8) * D_DIM + cc] =
                    __floats2bfloat162_rn(acc[mf][nf][2], acc[mf][nf][3]);
            } else {
                float* C = (PASS == 2) ? g_v : g_o;
                *(float2*)&C[r0 * D_DIM + cc] = make_float2(acc[mf][nf][0], acc[mf][nf][1]);
                *(float2*)&C[(r0 + 8) * D_DIM + cc] = make_float2(acc[mf][nf][2], acc[mf][nf][3]);
            }
        }
    }
}

// ---- BN + IF per channel s (grid (2048,3)); V: near-threshold exact recompute ----
__global__ __launch_bounds__(256) void k_bn_if(const float* __restrict__ wv) {
    const int s = blockIdx.x, y = blockIdx.y, tid = threadIdx.x;
    const int lane = tid & 31, wrp = tid >> 5;
    __nv_bfloat16* O = (y == 0) ? g_qs : (y == 1) ? g_ks : g_vs;
    const int base = s * D_DIM + tid;
    __shared__ float part[8];

    float vals[12];
    if (y == 2) {
#pragma unroll
        for (int t = 0; t < T_DIM; t++)
#pragma unroll
            for (int j = 0; j < 3; j++)
                vals[t * 3 + j] = g_v[t * SD + base + j * 256];
    } else {
        const __nv_bfloat16* Xb = (y == 0) ? g_qs : g_ks;
#pragma unroll
        for (int t = 0; t < T_DIM; t++)
#pragma unroll
            for (int j = 0; j < 3; j++)
                vals[t * 3 + j] = __bfloat162float(Xb[t * SD + base + j * 256]);
    }

    float lsum = 0.0f;
#pragma unroll
    for (int i = 0; i < 12; i++) lsum += vals[i];
#pragma unroll
    for (int o = 16; o; o >>= 1) lsum += __shfl_xor_sync(~0u, lsum, o);
    if (lane == 0) part[wrp] = lsum;
    __syncthreads();
    float tot = 0.0f;
#pragma unroll
    for (int w = 0; w < 8; w++) tot += part[w];
    const float mean = tot / 3072.0f;

    float lv = 0.0f;
#pragma unroll
    for (int i = 0; i < 12; i++) { float d = vals[i] - mean; lv += d * d; }
#pragma unroll
    for (int o = 16; o; o >>= 1) lv += __shfl_xor_sync(~0u, lv, o);
    __syncthreads();
    if (lane == 0) part[wrp] = lv;
    __syncthreads();
    float vtot = 0.0f;
#pragma unroll
    for (int w = 0; w < 8; w++) vtot += part[w];
    const float rs = rsqrtf(vtot / 3072.0f + 1e-5f);

#pragma unroll
    for (int j = 0; j < 3; j++) {
        const int d = tid + j * 256;
        float v = 0.0f, sp4[4];
        bool flag = false;
#pragma unroll
        for (int t = 0; t < T_DIM; t++) {
            float val = (vals[t * 3 + j] - mean) * rs;
            v += val;
            if (fabsf(v - 1.0f) < 3e-4f) flag = true;
            float sp = (v >= 1.0f) ? 1.0f : 0.0f;
            sp4[t] = sp;
            if (sp != 0.0f) v = 0.0f;
        }
        if (y == 2 && flag) {
            // exact ascending-k fp32 fma chain (matches reference GEMM order)
            float ex[4] = {0.0f, 0.0f, 0.0f, 0.0f};
            const __nv_bfloat16* sp0 = &g_spk0[s * D_DIM];
            for (int k = 0; k < D_DIM; k++) {
                float w = wv[k * D_DIM + d];
#pragma unroll
                for (int t = 0; t < T_DIM; t++)
                    ex[t] = fmaf(__bfloat162float(sp0[t * SD + k]), w, ex[t]);
            }
            v = 0.0f;
#pragma unroll
            for (int t = 0; t < T_DIM; t++) {
                float val = (ex[t] - mean) * rs;
                v += val;
                float sp = (v >= 1.0f) ? 1.0f : 0.0f;
                sp4[t] = sp;
                if (sp != 0.0f) v = 0.0f;
            }
        }
#pragma unroll
        for (int t = 0; t < T_DIM; t++)
            O[t * SD + base + j * 256] = __float2bfloat16(sp4[t]);
    }
}

// ---- QK counts (exact integer float atomics) + IF ----
__global__ void k_qk_partial() {
    const int t = blockIdx.x / 3;
    const int c = (blockIdx.x % 3) * 256 + threadIdx.x;
    const int s0 = blockIdx.y * 256;
    const __nv_bfloat16* Qp = &g_qs[t * SD + s0 * D_DIM + c];
    const __nv_bfloat16* Kp = &g_ks[t * SD + s0 * D_DIM + c];
    float acc = 0.0f;
#pragma unroll 8
    for (int s = 0; s < 256; s++)
        acc += __bfloat162float(Qp[s * D_DIM]) * __bfloat162float(Kp[s * D_DIM]);
    atomicAdd(&g_qk_raw[t * D_DIM + c], acc);
}
__global__ void k_qk_fin() {
    int c = blockIdx.x * blockDim.x + threadIdx.x;
    if (c >= D_DIM) return;
    float v = 0.0f;
#pragma unroll
    for (int t = 0; t < T_DIM; t++) {
        v += g_qk_raw[t * D_DIM + c];
        float sp = (v >= 1.0f) ? 1.0f : 0.0f;
        g_qkm[t * D_DIM + c] = __float2bfloat16(sp);
        if (sp != 0.0f) v = 0.0f;
    }
}

// ---- final BN -> out ----
__global__ void k_bn_out(float* __restrict__ out) {
    const int s = blockIdx.x, tid = threadIdx.x;
    const int lane = tid & 31, wrp = tid >> 5;
    __shared__ float part[8];
    const int base = s * D_DIM + tid;

    float vals[12];
#pragma unroll
    for (int t = 0; t < T_DIM; t++)
#pragma unroll
        for (int j = 0; j < 3; j++) vals[t * 3 + j] = g_o[t * SD + base + j * 256];

    float lsum = 0.0f;
#pragma unroll
    for (int i = 0; i < 12; i++) lsum += vals[i];
#pragma unroll
    for (int o = 16; o; o >>= 1) lsum += __shfl_xor_sync(~0u, lsum, o);
    if (lane == 0) part[wrp] = lsum;
    __syncthreads();
    float tot = 0.0f;
#pragma unroll
    for (int w = 0; w < 8; w++) tot += part[w];
    const float mean = tot / 3072.0f;

    float lv = 0.0f;
#pragma unroll
    for (int i = 0; i < 12; i++) { float d = vals[i] - mean; lv += d * d; }
#pragma unroll
    for (int o = 16; o; o >>= 1) lv += __shfl_xor_sync(~0u, lv, o);
    __syncthreads();
    if (lane == 0) part[wrp] = lv;
    __syncthreads();
    float vtot = 0.0f;
#pragma unroll
    for (int w = 0; w < 8; w++) vtot += part[w];
    const float rs = rsqrtf(vtot / 3072.0f + 1e-5f);

#pragma unroll
    for (int t = 0; t < T_DIM; t++)
#pragma unroll
        for (int j = 0; j < 3; j++)
            out[t * SD + base + j * 256] = (vals[t * 3 + j] - mean) * rs;
}

// ---- launch ----
extern "C" void kernel_launch(void* const* d_in, const int* in_sizes, int n_in,
                              void* d_out, int out_size) {
    const float* x  = (const float*)d_in[0];
    const float* wq = (const float*)d_in[1];
    const float* wk = (const float*)d_in[2];
    const float* wv = (const float*)d_in[3];
    const float* wo = (const float*)d_in[4];
    float* out = (float*)d_out;

    // smem: A NSTAGE*8K + B NSTAGE*TERMS*16K
    cudaFuncSetAttribute(k_mma<0>, cudaFuncAttributeMaxDynamicSharedMemorySize, 73728);
    cudaFuncSetAttribute(k_mma<2>, cudaFuncAttributeMaxDynamicSharedMemorySize, 114688);
    cudaFuncSetAttribute(k_mma<3>, cudaFuncAttributeMaxDynamicSharedMemorySize, 81920);

    k_prep<<<dim3(24, 24, 4), dim3(32, 8)>>>(wq, wk, wv, wo);
    k_init_spike<<<(SD + 255) / 256, 256>>>(x);

    k_mma<0><<<dim3(6, 128, 2), 256, 73728>>>();   // Q, K (bf16 out)
    k_mma<2><<<dim3(6, 128, 1), 256, 114688>>>();  // V (triple split, fp32 out)

    k_bn_if<<<dim3(S_DIM, 3), 256>>>(wv);

    k_qk_partial<<<dim3(12, 8), 256>>>();
    k_qk_fin<<<(D_DIM + 255) / 256, 256>>>();

    k_mma<3><<<dim3(6, 128, 1), 256, 81920>>>();   // O (double split, mask fused)

    k_bn_out<<<S_DIM, 256>>>(out);
}

// round 16
// speedup vs baseline: 2.0395x; 1.0479x over previous
#include <cuda_runtime.h>
#include <cuda_bf16.h>
#include <cstdint>

#define T_DIM 4
#define S_DIM 2048
#define D_DIM 768
#define SD (S_DIM * D_DIM)
#define TSD (T_DIM * SD)
#define DD (D_DIM * D_DIM)

// ---- device scratch (allocation-free) ----
__device__ __nv_bfloat16 g_spk0[TSD];          // init spikes (exact 0/1)
__device__ float g_v[TSD], g_o[TSD];           // pre-BN fp32 (V, O critical)
__device__ __nv_bfloat16 g_qs[TSD], g_ks[TSD]; // Q/K pre-BN bf16, then spikes (in-place)
__device__ __nv_bfloat16 g_vs[TSD];            // V spikes bf16
__device__ float g_qk_raw[T_DIM * D_DIM];
__device__ __nv_bfloat16 g_wqt[DD], g_wkt[DD]; // transposed [n][k] bf16
__device__ __nv_bfloat16 g_wvt[3 * DD];        // V: hi/lo/lo2 planes
__device__ __nv_bfloat16 g_wot[2 * DD];        // O: hi/lo planes

#define SWZ128(o) ((o) ^ (((o) >> 3) & 0x70))

__device__ __forceinline__ uint32_t smem_u32(const void* p) {
    uint32_t a;
    asm("{ .reg .u64 t; cvta.to.shared.u64 t, %1; cvt.u32.u64 %0, t; }"
        : "=r"(a) : "l"(p));
    return a;
}
__device__ __forceinline__ void cp16(uint32_t dst, const void* src) {
    asm volatile("cp.async.cg.shared.global [%0], [%1], 16;" :: "r"(dst), "l"(src));
}
__device__ __forceinline__ void cp_commit() {
    asm volatile("cp.async.commit_group;" ::: "memory");
}
__device__ __forceinline__ void ldm_x4(uint32_t addr, uint32_t& r0, uint32_t& r1,
                                       uint32_t& r2, uint32_t& r3) {
    asm volatile("ldmatrix.sync.aligned.m8n8.x4.shared.b16 {%0,%1,%2,%3}, [%4];"
                 : "=r"(r0), "=r"(r1), "=r"(r2), "=r"(r3) : "r"(addr));
}
__device__ __forceinline__ void mma16816(float* c, const uint32_t* a,
                                         uint32_t b0, uint32_t b1) {
    asm volatile(
        "mma.sync.aligned.m16n8k16.row.col.f32.bf16.bf16.f32 "
        "{%0,%1,%2,%3}, {%4,%5,%6,%7}, {%8,%9}, {%0,%1,%2,%3};"
        : "+f"(c[0]), "+f"(c[1]), "+f"(c[2]), "+f"(c[3])
        : "r"(a[0]), "r"(a[1]), "r"(a[2]), "r"(a[3]), "r"(b0), "r"(b1));
}

// ---- weight prep: transpose + bf16 split ----
__global__ void k_prep(const float* __restrict__ wq, const float* __restrict__ wk,
                       const float* __restrict__ wv, const float* __restrict__ wo) {
    __shared__ float tile[32][33];
    const int z = blockIdx.z;
    const float* W = (z == 0) ? wq : (z == 1) ? wk : (z == 2) ? wv : wo;
    const int k0 = blockIdx.x * 32, n0 = blockIdx.y * 32;
    const int tx = threadIdx.x, ty = threadIdx.y;
    for (int i = ty; i < 32; i += 8) tile[i][tx] = W[(k0 + i) * D_DIM + n0 + tx];
    __syncthreads();
    for (int i = ty; i < 32; i += 8) {
        int n = n0 + i, k = k0 + tx;
        float w = tile[tx][i];
        __nv_bfloat16 hi = __float2bfloat16(w);
        if (z == 0) g_wqt[n * D_DIM + k] = hi;
        else if (z == 1) g_wkt[n * D_DIM + k] = hi;
        else {
            float r1 = w - __bfloat162float(hi);
            __nv_bfloat16 lo = __float2bfloat16(r1);
            if (z == 2) {
                g_wvt[n * D_DIM + k] = hi;
                g_wvt[DD + n * D_DIM + k] = lo;
                g_wvt[2 * DD + n * D_DIM + k] =
                    __float2bfloat16(r1 - __bfloat162float(lo));
            } else {
                g_wot[n * D_DIM + k] = hi;
                g_wot[DD + n * D_DIM + k] = lo;
            }
        }
    }
}

// init spikes + zero QK accumulator (merged)
__global__ void k_init_spike(const float* __restrict__ x) {
    int idx = blockIdx.x * blockDim.x + threadIdx.x;
    if (idx < T_DIM * D_DIM) g_qk_raw[idx] = 0.0f;
    if (idx >= SD) return;
    float v = 0.0f;
#pragma unroll
    for (int t = 0; t < T_DIM; t++) {
        v += x[t * SD + idx];
        float sp = (v >= 1.0f) ? 1.0f : 0.0f;
        g_spk0[t * SD + idx] = __float2bfloat16(sp);
        if (sp != 0.0f) v = 0.0f;
    }
}

// ---------------------------------------------------------------------------
// GEMM core: CTA 64x128, BK=64, 8 warps (2m x 4n), warp 32x32.
// Canonical multistage: wait -> sync -> fill(next) -> compute. ONE sync/chunk.
// TERMS B-planes accumulate into the same accumulators (weight splitting).
// MASKED: A fill multiplied by smem mask (exact 0/1 product, sync stores).
// ---------------------------------------------------------------------------
template <int TERMS, int NSTAGE, bool MASKED, bool BF16OUT>
__device__ __forceinline__ void gemm_run(char* smp, uint32_t smp_u,
                                         const __nv_bfloat16* __restrict__ A,
                                         const __nv_bfloat16* __restrict__ B,
                                         float* Cf, __nv_bfloat16* Cb,
                                         const __nv_bfloat16* maskS,
                                         int m0, int n0) {
    const int tid = threadIdx.x, wid = tid >> 5, lane = tid & 31;
    const int wm = wid & 1, wn = wid >> 1;
    const int lrow = lane & 15, lsel = lane >> 4;

    auto A_off = [&](int st) { return (uint32_t)(st * 8192); };
    auto B_off = [&](int st, int term) {
        return (uint32_t)(NSTAGE * 8192 + (st * TERMS + term) * 16384);
    };

    auto fillA = [&](int chunk, int st) {
        const int k0 = chunk * 64;
#pragma unroll
        for (int c = 0; c < 2; c++) {
            int idx = tid + c * 256;
            int r = idx >> 3, cc = idx & 7;
            if (MASKED) {
                uint4 v = *(const uint4*)&A[(m0 + r) * D_DIM + k0 + cc * 8];
                uint4 mv = *(const uint4*)&maskS[k0 + cc * 8];
                __nv_bfloat162* vv = (__nv_bfloat162*)&v;
                const __nv_bfloat162* mm = (const __nv_bfloat162*)&mv;
                vv[0] = __hmul2(vv[0], mm[0]); vv[1] = __hmul2(vv[1], mm[1]);
                vv[2] = __hmul2(vv[2], mm[2]); vv[3] = __hmul2(vv[3], mm[3]);
                *(uint4*)(smp + A_off(st) + SWZ128((uint32_t)(r * 128 + cc * 16))) = v;
            } else {
                cp16(smp_u + A_off(st) + SWZ128((uint32_t)(r * 128 + cc * 16)),
                     &A[(m0 + r) * D_DIM + k0 + cc * 8]);
            }
        }
    };
    auto fillB = [&](int chunk, int st) {
        const int k0 = chunk * 64;
#pragma unroll
        for (int term = 0; term < TERMS; term++) {
            const __nv_bfloat16* Bp = B + term * DD;
#pragma unroll
            for (int c = 0; c < 4; c++) {
                int idx = tid + c * 256;
                int r = idx >> 3, cc = idx & 7;
                cp16(smp_u + B_off(st, term) + SWZ128((uint32_t)(r * 128 + cc * 16)),
                     &Bp[(n0 + r) * D_DIM + k0 + cc * 8]);
            }
        }
    };

    float acc[2][4][4];
#pragma unroll
    for (int i = 0; i < 2; i++)
#pragma unroll
        for (int j = 0; j < 4; j++)
#pragma unroll
            for (int e = 0; e < 4; e++) acc[i][j][e] = 0.0f;

    // prologue: NSTAGE-1 stages in flight
#pragma unroll
    for (int s = 0; s < NSTAGE - 1; s++) {
        fillA(s, s); fillB(s, s); cp_commit();
    }

    uint32_t afr[2][2][4], bfr[2][2][4];

    for (int i = 0; i < 12; i++) {
        const int st = i % NSTAGE;
        // wait for chunk i's group, then align all warps
        if (NSTAGE == 3) {
            if (i < 11) { asm volatile("cp.async.wait_group 1;" ::: "memory"); }
            else        { asm volatile("cp.async.wait_group 0;" ::: "memory"); }
        } else {
            asm volatile("cp.async.wait_group 0;" ::: "memory");
        }
        __syncthreads();
        // now safe to overwrite the oldest stage
        const int nf = i + NSTAGE - 1;
        if (nf < 12) { fillA(nf, nf % NSTAGE); fillB(nf, nf % NSTAGE); cp_commit(); }

        auto ldA = [&](int buf, int kk) {
#pragma unroll
            for (int mf = 0; mf < 2; mf++) {
                uint32_t row = (uint32_t)(wm * 32 + mf * 16 + lrow);
                uint32_t addr = smp_u + A_off(st) +
                                SWZ128(row * 128 + (uint32_t)(kk * 2 + lsel) * 16);
                ldm_x4(addr, afr[buf][mf][0], afr[buf][mf][1],
                       afr[buf][mf][2], afr[buf][mf][3]);
            }
        };
        auto ldB = [&](int buf, int kk, int term) {
#pragma unroll
            for (int bh = 0; bh < 2; bh++) {
                uint32_t row = (uint32_t)(wn * 32 + bh * 16 + lrow);
                uint32_t addr = smp_u + B_off(st, term) +
                                SWZ128(row * 128 + (uint32_t)(kk * 2 + lsel) * 16);
                ldm_x4(addr, bfr[buf][bh][0], bfr[buf][bh][1],
                       bfr[buf][bh][2], bfr[buf][bh][3]);
            }
        };

        ldA(0, 0); ldB(0, 0, 0);
#pragma unroll
        for (int kk = 0; kk < 4; kk++) {
#pragma unroll
            for (int term = 0; term < TERMS; term++) {
                const int cur = (kk * TERMS + term) & 1;
                const int nxt = cur ^ 1;
                if (term + 1 < TERMS) ldB(nxt, kk, term + 1);
                else if (kk + 1 < 4) ldB(nxt, kk + 1, 0);
                if (term == TERMS - 1 && kk + 1 < 4) ldA((kk + 1) & 1, kk + 1);
                const int ab = kk & 1;
#pragma unroll
                for (int bh = 0; bh < 2; bh++)
#pragma unroll
                    for (int mf = 0; mf < 2; mf++) {
                        mma16816(acc[mf][bh * 2 + 0], afr[ab][mf],
                                 bfr[cur][bh][0], bfr[cur][bh][2]);
                        mma16816(acc[mf][bh * 2 + 1], afr[ab][mf],
                                 bfr[cur][bh][1], bfr[cur][bh][3]);
                    }
            }
        }
    }

    // epilogue
#pragma unroll
    for (int mf = 0; mf < 2; mf++) {
        int r0 = m0 + wm * 32 + mf * 16 + (lane >> 2);
#pragma unroll
        for (int nf = 0; nf < 4; nf++) {
            int cc = n0 + wn * 32 + nf * 8 + (lane & 3) * 2;
            if (BF16OUT) {
                *(__nv_bfloat162*)&Cb[r0 * D_DIM + cc] =
                    __floats2bfloat162_rn(acc[mf][nf][0], acc[mf][nf][1]);
                *(__nv_bfloat162*)&Cb[(r0 + 8) * D_DIM + cc] =
                    __floats2bfloat162_rn(acc[mf][nf][2], acc[mf][nf][3]);
            } else {
                *(float2*)&Cf[r0 * D_DIM + cc] = make_float2(acc[mf][nf][0], acc[mf][nf][1]);
                *(float2*)&Cf[(r0 + 8) * D_DIM + cc] = make_float2(acc[mf][nf][2], acc[mf][nf][3]);
            }
        }
    }
}

// merged Q/K/V GEMM launch: z=0 Q, z=1 K (1 term, bf16 out); z=2 V (3 terms, fp32)
__global__ __launch_bounds__(256, 2) void k_mma_qkv() {
    extern __shared__ __align__(16) char smp[];
    const uint32_t smp_u = smem_u32(smp);
    const int n0 = blockIdx.x * 128, m0 = blockIdx.y * 64;
    const int z = blockIdx.z;
    if (z == 0)
        gemm_run<1, 3, false, true>(smp, smp_u, g_spk0, g_wqt, nullptr, g_qs,
                                    nullptr, m0, n0);
    else if (z == 1)
        gemm_run<1, 3, false, true>(smp, smp_u, g_spk0, g_wkt, nullptr, g_ks,
                                    nullptr, m0, n0);
    else
        gemm_run<3, 2, false, false>(smp, smp_u, g_spk0, g_wvt, g_v, nullptr,
                                     nullptr, m0, n0);
}

// O GEMM: mask derived in-kernel from g_qk_raw (fused qk_fin), 2 terms, fp32 out
__global__ __launch_bounds__(256, 2) void k_mma_o() {
    extern __shared__ __align__(16) char smp[];
    __shared__ __align__(16) __nv_bfloat16 maskS[D_DIM];
    const int n0 = blockIdx.x * 128, m0 = blockIdx.y * 64;
    const int t_idx = m0 >> 11;
    const int tid = threadIdx.x;
    for (int c = tid; c < D_DIM; c += 256) {
        float v = 0.0f, spt = 0.0f;
#pragma unroll
        for (int t = 0; t < T_DIM; t++) {
            v += g_qk_raw[t * D_DIM + c];
            float sp = (v >= 1.0f) ? 1.0f : 0.0f;
            if (t == t_idx) spt = sp;
            if (sp != 0.0f) v = 0.0f;
        }
        maskS[c] = __float2bfloat16(spt);
    }
    __syncthreads();
    gemm_run<2, 2, true, false>(smp, smem_u32(smp), g_vs, g_wot, g_o, nullptr,
                                maskS, m0, n0);
}

// ---- BN + IF for Q/K (bf16 in, spikes out in-place). grid (2048, 2) ----
__global__ __launch_bounds__(256) void k_bn_qk() {
    const int s = blockIdx.x, y = blockIdx.y, tid = threadIdx.x;
    const int lane = tid & 31, wrp = tid >> 5;
    __nv_bfloat16* X = (y == 0) ? g_qs : g_ks;
    const int base = s * D_DIM + tid;
    __shared__ float part[8];

    float vals[12];
#pragma unroll
    for (int t = 0; t < T_DIM; t++)
#pragma unroll
        for (int j = 0; j < 3; j++)
            vals[t * 3 + j] = __bfloat162float(X[t * SD + base + j * 256]);

    float lsum = 0.0f;
#pragma unroll
    for (int i = 0; i < 12; i++) lsum += vals[i];
#pragma unroll
    for (int o = 16; o; o >>= 1) lsum += __shfl_xor_sync(~0u, lsum, o);
    if (lane == 0) part[wrp] = lsum;
    __syncthreads();
    float tot = 0.0f;
#pragma unroll
    for (int w = 0; w < 8; w++) tot += part[w];
    const float mean = tot / 3072.0f;

    float lv = 0.0f;
#pragma unroll
    for (int i = 0; i < 12; i++) { float d = vals[i] - mean; lv += d * d; }
#pragma unroll
    for (int o = 16; o; o >>= 1) lv += __shfl_xor_sync(~0u, lv, o);
    __syncthreads();
    if (lane == 0) part[wrp] = lv;
    __syncthreads();
    float vtot = 0.0f;
#pragma unroll
    for (int w = 0; w < 8; w++) vtot += part[w];
    const float rs = rsqrtf(vtot / 3072.0f + 1e-5f);

#pragma unroll
    for (int j = 0; j < 3; j++) {
        float v = 0.0f;
#pragma unroll
        for (int t = 0; t < T_DIM; t++) {
            float val = (vals[t * 3 + j] - mean) * rs;
            v += val;
            float sp = (v >= 1.0f) ? 1.0f : 0.0f;
            X[t * SD + base + j * 256] = __float2bfloat16(sp);
            if (sp != 0.0f) v = 0.0f;
        }
    }
}

// ---- BN + IF for V (fp32 in) with near-threshold exact recompute. grid 2048 ----
__global__ __launch_bounds__(256) void k_bn_v(const float* __restrict__ wv) {
    const int s = blockIdx.x, tid = threadIdx.x;
    const int lane = tid & 31, wrp = tid >> 5;
    const int base = s * D_DIM + tid;
    __shared__ float part[8];

    float vals[12];
#pragma unroll
    for (int t = 0; t < T_DIM; t++)
#pragma unroll
        for (int j = 0; j < 3; j++)
            vals[t * 3 + j] = g_v[t * SD + base + j * 256];

    float lsum = 0.0f;
#pragma unroll
    for (int i = 0; i < 12; i++) lsum += vals[i];
#pragma unroll
    for (int o = 16; o; o >>= 1) lsum += __shfl_xor_sync(~0u, lsum, o);
    if (lane == 0) part[wrp] = lsum;
    __syncthreads();
    float tot = 0.0f;
#pragma unroll
    for (int w = 0; w < 8; w++) tot += part[w];
    const float mean = tot / 3072.0f;

    float lv = 0.0f;
#pragma unroll
    for (int i = 0; i < 12; i++) { float d = vals[i] - mean; lv += d * d; }
#pragma unroll
    for (int o = 16; o; o >>= 1) lv += __shfl_xor_sync(~0u, lv, o);
    __syncthreads();
    if (lane == 0) part[wrp] = lv;
    __syncthreads();
    float vtot = 0.0f;
#pragma unroll
    for (int w = 0; w < 8; w++) vtot += part[w];
    const float rs = rsqrtf(vtot / 3072.0f + 1e-5f);

#pragma unroll
    for (int j = 0; j < 3; j++) {
        const int d = tid + j * 256;
        float v = 0.0f, sp4[4];
        bool flag = false;
#pragma unroll
        for (int t = 0; t < T_DIM; t++) {
            float val = (vals[t * 3 + j] - mean) * rs;
            v += val;
            if (fabsf(v - 1.0f) < 3e-4f) flag = true;
            float sp = (v >= 1.0f) ? 1.0f : 0.0f;
            sp4[t] = sp;
            if (sp != 0.0f) v = 0.0f;
        }
        if (flag) {
            // exact ascending-k fp32 fma chain (matches reference GEMM order)
            float ex[4] = {0.0f, 0.0f, 0.0f, 0.0f};
            const __nv_bfloat16* sp0 = &g_spk0[s * D_DIM];
            for (int k = 0; k < D_DIM; k++) {
                float w = wv[k * D_DIM + d];
#pragma unroll
                for (int t = 0; t < T_DIM; t++)
                    ex[t] = fmaf(__bfloat162float(sp0[t * SD + k]), w, ex[t]);
            }
            v = 0.0f;
#pragma unroll
            for (int t = 0; t < T_DIM; t++) {
                float val = (ex[t] - mean) * rs;
                v += val;
                float sp = (v >= 1.0f) ? 1.0f : 0.0f;
                sp4[t] = sp;
                if (sp != 0.0f) v = 0.0f;
            }
        }
#pragma unroll
        for (int t = 0; t < T_DIM; t++)
            g_vs[t * SD + base + j * 256] = __float2bfloat16(sp4[t]);
    }
}

// ---- QK counts (exact integer float atomics). grid (12, 32) ----
__global__ void k_qk_partial() {
    const int t = blockIdx.x / 3;
    const int c = (blockIdx.x % 3) * 256 + threadIdx.x;
    const int s0 = blockIdx.y * 64;
    const __nv_bfloat16* Qp = &g_qs[t * SD + s0 * D_DIM + c];
    const __nv_bfloat16* Kp = &g_ks[t * SD + s0 * D_DIM + c];
    float acc = 0.0f;
#pragma unroll 8
    for (int s = 0; s < 64; s++)
        acc += __bfloat162float(Qp[s * D_DIM]) * __bfloat162float(Kp[s * D_DIM]);
    atomicAdd(&g_qk_raw[t * D_DIM + c], acc);
}

// ---- final BN -> out ----
__global__ void k_bn_out(float* __restrict__ out) {
    const int s = blockIdx.x, tid = threadIdx.x;
    const int lane = tid & 31, wrp = tid >> 5;
    __shared__ float part[8];
    const int base = s * D_DIM + tid;

    float vals[12];
#pragma unroll
    for (int t = 0; t < T_DIM; t++)
#pragma unroll
        for (int j = 0; j < 3; j++) vals[t * 3 + j] = g_o[t * SD + base + j * 256];

    float lsum = 0.0f;
#pragma unroll
    for (int i = 0; i < 12; i++) lsum += vals[i];
#pragma unroll
    for (int o = 16; o; o >>= 1) lsum += __shfl_xor_sync(~0u, lsum, o);
    if (lane == 0) part[wrp] = lsum;
    __syncthreads();
    float tot = 0.0f;
#pragma unroll
    for (int w = 0; w < 8; w++) tot += part[w];
    const float mean = tot / 3072.0f;

    float lv = 0.0f;
#pragma unroll
    for (int i = 0; i < 12; i++) { float d = vals[i] - mean; lv += d * d; }
#pragma unroll
    for (int o = 16; o; o >>= 1) lv += __shfl_xor_sync(~0u, lv, o);
    __syncthreads();
    if (lane == 0) part[wrp] = lv;
    __syncthreads();
    float vtot = 0.0f;
#pragma unroll
    for (int w = 0; w < 8; w++) vtot += part[w];
    const float rs = rsqrtf(vtot / 3072.0f + 1e-5f);

#pragma unroll
    for (int t = 0; t < T_DIM; t++)
#pragma unroll
        for (int j = 0; j < 3; j++)
            out[t * SD + base + j * 256] = (vals[t * 3 + j] - mean) * rs;
}

// ---- launch ----
extern "C" void kernel_launch(void* const* d_in, const int* in_sizes, int n_in,
                              void* d_out, int out_size) {
    const float* x  = (const float*)d_in[0];
    const float* wq = (const float*)d_in[1];
    const float* wk = (const float*)d_in[2];
    const float* wv = (const float*)d_in[3];
    const float* wo = (const float*)d_in[4];
    float* out = (float*)d_out;

    // QKV: max stage need = V (2 stages x (8K A + 48K B)) = 112K; O: 80K
    cudaFuncSetAttribute(k_mma_qkv, cudaFuncAttributeMaxDynamicSharedMemorySize, 114688);
    cudaFuncSetAttribute(k_mma_o,   cudaFuncAttributeMaxDynamicSharedMemorySize, 81920);

    k_prep<<<dim3(24, 24, 4), dim3(32, 8)>>>(wq, wk, wv, wo);
    k_init_spike<<<(SD + 255) / 256, 256>>>(x);

    k_mma_qkv<<<dim3(6, 128, 3), 256, 114688>>>();   // Q, K, V in one launch

    k_bn_qk<<<dim3(S_DIM, 2), 256>>>();
    k_bn_v<<<S_DIM, 256>>>(wv);

    k_qk_partial<<<dim3(12, 32), 256>>>();

    k_mma_o<<<dim3(6, 128), 256, 81920>>>();         // O (mask fused from qk_raw)

    k_bn_out<<<S_DIM, 256>>>(out);
}